// round 7
// baseline (speedup 1.0000x reference)
#include <cuda_runtime.h>
#include <cuda_fp16.h>
#include <math_constants.h>
#include <cstdint>
#include <cstddef>

#define BB 2
#define NQ 4096
#define NKV 1024
#define DD 512
#define HH 8
#define DH 64
#define LN_EPS 1e-5f

// ---------------------------------------------------------------------------
// Scratch
// ---------------------------------------------------------------------------
__device__ float g_qh[BB * NQ * DD];
__device__ float g_kh[BB * NKV * DD];
__device__ float g_vh[BB * NKV * DD];
__device__ float g_attn[BB * NQ * DD];
__device__ float2 g_stats[BB * NQ];      // per-row (mean, rstd)
__device__ __half g_wt[4 * DD * DD];     // W^T, fp16, [n][k] k-contiguous

// ---------------------------------------------------------------------------
// helpers
// ---------------------------------------------------------------------------
__device__ __forceinline__ uint32_t packh2(float lo, float hi) {
    uint32_t r;
    asm("cvt.rn.f16x2.f32 %0, %1, %2;" : "=r"(r) : "f"(hi), "f"(lo));
    return r;
}

__device__ __forceinline__ float ex2(float x) {
    float r;
    asm("ex2.approx.f32 %0, %1;" : "=f"(r) : "f"(x));
    return r;
}

__device__ __forceinline__ void mma_f16(float d[4], const uint32_t a[4],
                                        const uint32_t b[2]) {
    asm("mma.sync.aligned.m16n8k16.row.col.f32.f16.f16.f32 "
        "{%0,%1,%2,%3},{%4,%5,%6,%7},{%8,%9},{%0,%1,%2,%3};"
        : "+f"(d[0]), "+f"(d[1]), "+f"(d[2]), "+f"(d[3])
        : "r"(a[0]), "r"(a[1]), "r"(a[2]), "r"(a[3]), "r"(b[0]), "r"(b[1]));
}

// ---------------------------------------------------------------------------
// Weight transpose + fp16 convert: Wt[z][n][k] = fp16(W_z[k][n])
// ---------------------------------------------------------------------------
__global__ void __launch_bounds__(256) transpose_w(
    const float* __restrict__ Wq, const float* __restrict__ Wk,
    const float* __restrict__ Wv, const float* __restrict__ Wo,
    __half* __restrict__ Wt)
{
    __shared__ float t[32][33];
    const int z = blockIdx.z;
    const float* W = (z == 0) ? Wq : (z == 1) ? Wk : (z == 2) ? Wv : Wo;
    __half* T = Wt + (size_t)z * DD * DD;
    const int tx = threadIdx.x, ty = threadIdx.y;
    const int kb = blockIdx.x * 32, nb = blockIdx.y * 32;
    #pragma unroll
    for (int j = 0; j < 4; j++)
        t[ty + j * 8][tx] = W[(size_t)(kb + ty + j * 8) * DD + nb + tx];
    __syncthreads();
    #pragma unroll
    for (int j = 0; j < 4; j++)
        T[(size_t)(nb + ty + j * 8) * DD + kb + tx] =
            __float2half_rn(t[tx][ty + j * 8]);
}

// ---------------------------------------------------------------------------
// Row stats for LN fusion: one warp per row of X[*, 512]
// ---------------------------------------------------------------------------
__global__ void __launch_bounds__(256) rowstats(
    const float* __restrict__ X, float2* __restrict__ st)
{
    const int w = threadIdx.x >> 5, lane = threadIdx.x & 31;
    const int row = blockIdx.x * 8 + w;
    const float* x = X + (size_t)row * DD;
    float s = 0.f, sq = 0.f;
    #pragma unroll
    for (int j = 0; j < 4; j++) {
        const float4 v = *(const float4*)(x + lane * 4 + j * 128);
        s += v.x + v.y + v.z + v.w;
        sq += v.x * v.x + v.y * v.y + v.z * v.z + v.w * v.w;
    }
    #pragma unroll
    for (int off = 16; off > 0; off >>= 1) {
        s += __shfl_xor_sync(0xffffffffu, s, off);
        sq += __shfl_xor_sync(0xffffffffu, sq, off);
    }
    if (lane == 0) {
        const float mean = s * (1.f / DD);
        const float var = sq * (1.f / DD) - mean * mean;
        st[row] = make_float2(mean, rsqrtf(var + LN_EPS));
    }
}

// ---------------------------------------------------------------------------
// fp16 GEMM: C[M,512] = A'[M,512] @ W (+bias). Wt = W^T fp16 [n][k].
// A' = A, or LayerNorm(A) applied in the loader (LNF: stats + gamma/beta).
// BM=64, BN=128, BK=32, 256 threads, warps 2(M)x4(N), warp tile 32x32.
// blockIdx.z selects (Wt0,C0)/(Wt1,C1).
// ---------------------------------------------------------------------------
template <bool BIAS, bool LNF>
__global__ void __launch_bounds__(256) gemm_f16(
    const float* __restrict__ A, const __half* __restrict__ Wt0,
    const __half* __restrict__ Wt1, const float* __restrict__ bias,
    const float2* __restrict__ stats, const float* __restrict__ gamma,
    const float* __restrict__ beta,
    float* __restrict__ C0, float* __restrict__ C1)
{
    __shared__ uint32_t As[64 * 20];
    __shared__ uint32_t Bs[128 * 20];

    const __half* __restrict__ Wt = blockIdx.z ? Wt1 : Wt0;
    float* __restrict__ C = blockIdx.z ? C1 : C0;

    const int tid = threadIdx.x;
    const int lane = tid & 31;
    const int g = lane >> 2, t = lane & 3;
    const int w = tid >> 5;
    const int wm = w >> 2, wn = w & 3;
    const int row0 = blockIdx.y * 64, col0 = blockIdx.x * 128;

    // A loader: 64 rows x 8 float4 = 512 units, 2/thread
    const int ar = tid >> 3;            // + i*32
    const int af4 = tid & 7;
    // B loader: 128 rows x 4 uint4 = 512 units, 2/thread
    const int br = tid >> 2;            // + i*64
    const int bf = tid & 3;

    float a_sc[2], a_sh[2];   // LNF: per-row scale/shift (x*sc + sh = (x-mu)*rs)
    if (LNF) {
        #pragma unroll
        for (int i = 0; i < 2; i++) {
            const float2 st = stats[row0 + ar + i * 32];
            a_sc[i] = st.y;
            a_sh[i] = -st.x * st.y;
        }
    }

    float4 aR[2];
    uint4 bR[2];

    auto loadA = [&](int k0) {
        #pragma unroll
        for (int i = 0; i < 2; i++)
            aR[i] = *(const float4*)(A + (size_t)(row0 + ar + i * 32) * DD + k0 + af4 * 4);
    };
    auto loadB = [&](int k0) {
        #pragma unroll
        for (int i = 0; i < 2; i++)
            bR[i] = *(const uint4*)(Wt + (size_t)(col0 + br + i * 64) * DD + k0 + bf * 8);
    };

    float acc[2][4][4];
    #pragma unroll
    for (int mi = 0; mi < 2; mi++)
        #pragma unroll
        for (int ni = 0; ni < 4; ni++)
            #pragma unroll
            for (int r = 0; r < 4; r++) acc[mi][ni][r] = 0.f;

    loadA(0);
    loadB(0);

    for (int k0 = 0; k0 < DD; k0 += 32) {
        float4 g4, b4;
        if (LNF) {
            g4 = *(const float4*)(gamma + k0 + af4 * 4);
            b4 = *(const float4*)(beta + k0 + af4 * 4);
        }
        #pragma unroll
        for (int i = 0; i < 2; i++) {
            float4 v = aR[i];
            if (LNF) {
                v.x = fmaf(v.x, a_sc[i], a_sh[i]) * g4.x + b4.x;
                v.y = fmaf(v.y, a_sc[i], a_sh[i]) * g4.y + b4.y;
                v.z = fmaf(v.z, a_sc[i], a_sh[i]) * g4.z + b4.z;
                v.w = fmaf(v.w, a_sc[i], a_sh[i]) * g4.w + b4.w;
            }
            *(uint2*)&As[(ar + i * 32) * 20 + af4 * 2] =
                make_uint2(packh2(v.x, v.y), packh2(v.z, v.w));
        }
        #pragma unroll
        for (int i = 0; i < 2; i++)
            *(uint4*)&Bs[(br + i * 64) * 20 + bf * 4] = bR[i];
        __syncthreads();

        if (k0 + 32 < DD) { loadA(k0 + 32); loadB(k0 + 32); }

        #pragma unroll
        for (int ks = 0; ks < 2; ks++) {
            const int ko = ks * 8;
            uint32_t af[2][4];
            #pragma unroll
            for (int mi = 0; mi < 2; mi++) {
                const int mb = wm * 32 + mi * 16;
                af[mi][0] = As[(mb + g) * 20 + ko + t];
                af[mi][1] = As[(mb + g + 8) * 20 + ko + t];
                af[mi][2] = As[(mb + g) * 20 + ko + t + 4];
                af[mi][3] = As[(mb + g + 8) * 20 + ko + t + 4];
            }
            #pragma unroll
            for (int ni = 0; ni < 4; ni++) {
                const int nb = wn * 32 + ni * 8;
                uint32_t bf2[2];
                bf2[0] = Bs[(nb + g) * 20 + ko + t];
                bf2[1] = Bs[(nb + g) * 20 + ko + t + 4];
                mma_f16(acc[0][ni], af[0], bf2);
                mma_f16(acc[1][ni], af[1], bf2);
            }
        }
        __syncthreads();
    }

    #pragma unroll
    for (int mi = 0; mi < 2; mi++) {
        const int rr0 = row0 + wm * 32 + mi * 16 + g;
        #pragma unroll
        for (int ni = 0; ni < 4; ni++) {
            const int cc = col0 + wn * 32 + ni * 8 + 2 * t;
            float2 v0 = make_float2(acc[mi][ni][0], acc[mi][ni][1]);
            float2 v1 = make_float2(acc[mi][ni][2], acc[mi][ni][3]);
            if (BIAS) {
                const float2 bv = *(const float2*)(bias + cc);
                v0.x += bv.x; v0.y += bv.y;
                v1.x += bv.x; v1.y += bv.y;
            }
            *(float2*)(C + (size_t)rr0 * DD + cc) = v0;
            *(float2*)(C + (size_t)(rr0 + 8) * DD + cc) = v1;
        }
    }
}

// ---------------------------------------------------------------------------
// Flash attention, fp16 mma, MAX-FREE softmax (scores analytically bounded;
// softmax is shift-invariant, exp2 domain with log2e folded into Q scale).
// Block = 128 queries x (b,h). 8 warps x 16 rows. l = plain sum, reduced once.
// ---------------------------------------------------------------------------
__global__ void __launch_bounds__(256) attn_f16(
    const float* __restrict__ Qh, const float* __restrict__ Kh,
    const float* __restrict__ Vh, float* __restrict__ O)
{
    __shared__ uint32_t Qs[128 * 36];
    __shared__ uint32_t Ks[64 * 36];
    __shared__ uint32_t Vs[32 * 68];

    const int tile = (NQ / 128 - 1) - blockIdx.x;   // big tiles first
    const int h = blockIdx.y, b = blockIdx.z;
    const int tid = threadIdx.x;
    const int lane = tid & 31;
    const int g = lane >> 2, t = lane & 3;
    const int w = tid >> 5;

    const size_t qbase = ((size_t)b * NQ + (size_t)tile * 128) * DD + (size_t)h * DH;
    const size_t kvbase = (size_t)b * NKV * DD + (size_t)h * DH;

    // Q tile, scaled by (1/8)*log2(e) so scores are in exp2 domain
    const float qsc = 0.125f * 1.4426950408889634f;
    #pragma unroll
    for (int i = 0; i < 8; i++) {
        const int idx = tid + i * 256;
        const int r = idx >> 4, c4 = idx & 15;
        const float4 v = *(const float4*)(Qh + qbase + (size_t)r * DD + c4 * 4);
        *(uint2*)&Qs[r * 36 + c4 * 2] =
            make_uint2(packh2(v.x * qsc, v.y * qsc), packh2(v.z * qsc, v.w * qsc));
    }

    float oacc[8][4];
    #pragma unroll
    for (int ni = 0; ni < 8; ni++)
        #pragma unroll
        for (int r = 0; r < 4; r++) oacc[ni][r] = 0.f;
    float l0 = 0.f, l1 = 0.f;

    const int row0 = tile * 128 + w * 16 + g;
    const int lim0 = row0 >> 2;
    const int lim1 = (row0 + 8) >> 2;
    const int nch = (32 * tile + 95) >> 6;

    for (int c = 0; c < nch; c++) {
        const int k0 = c * 64;
        __syncthreads();    // protect Ks/Vs from previous readers

        #pragma unroll
        for (int i = 0; i < 4; i++) {
            const int idx = tid + i * 256;
            const int r = idx >> 4, c4 = idx & 15;
            const float4 v = *(const float4*)(Kh + kvbase + (size_t)(k0 + r) * DD + c4 * 4);
            *(uint2*)&Ks[r * 36 + c4 * 2] =
                make_uint2(packh2(v.x, v.y), packh2(v.z, v.w));
        }
        #pragma unroll
        for (int i = 0; i < 2; i++) {
            const int idx = tid + i * 256;
            const int jp = idx >> 4, d4 = idx & 15;
            const float4 r0 = *(const float4*)(Vh + kvbase + (size_t)(k0 + 2 * jp) * DD + d4 * 4);
            const float4 r1 = *(const float4*)(Vh + kvbase + (size_t)(k0 + 2 * jp + 1) * DD + d4 * 4);
            uint4 u;
            u.x = packh2(r0.x, r1.x); u.y = packh2(r0.y, r1.y);
            u.z = packh2(r0.z, r1.z); u.w = packh2(r0.w, r1.w);
            *(uint4*)&Vs[jp * 68 + d4 * 4] = u;
        }
        __syncthreads();

        // S = Q @ K^T (log2 domain)
        float pf[8][4];
        #pragma unroll
        for (int ni = 0; ni < 8; ni++)
            #pragma unroll
            for (int r = 0; r < 4; r++) pf[ni][r] = 0.f;

        const int mb = w * 16;
        #pragma unroll
        for (int kt = 0; kt < 4; kt++) {
            const int ko = kt * 8;
            uint32_t af[4];
            af[0] = Qs[(mb + g) * 36 + ko + t];
            af[1] = Qs[(mb + g + 8) * 36 + ko + t];
            af[2] = Qs[(mb + g) * 36 + ko + t + 4];
            af[3] = Qs[(mb + g + 8) * 36 + ko + t + 4];
            #pragma unroll
            for (int ni = 0; ni < 8; ni++) {
                uint32_t bf2[2];
                bf2[0] = Ks[(ni * 8 + g) * 36 + ko + t];
                bf2[1] = Ks[(ni * 8 + g) * 36 + ko + t + 4];
                mma_f16(pf[ni], af, bf2);
            }
        }

        // p = 2^s (masked to 0 on the diagonal chunk); l accumulates unscaled
        if (c == nch - 1) {
            #pragma unroll
            for (int ni = 0; ni < 8; ni++) {
                const int j = k0 + ni * 8 + 2 * t;
                pf[ni][0] = (j     <= lim0) ? ex2(pf[ni][0]) : 0.f;
                pf[ni][1] = (j + 1 <= lim0) ? ex2(pf[ni][1]) : 0.f;
                pf[ni][2] = (j     <= lim1) ? ex2(pf[ni][2]) : 0.f;
                pf[ni][3] = (j + 1 <= lim1) ? ex2(pf[ni][3]) : 0.f;
                l0 += pf[ni][0] + pf[ni][1];
                l1 += pf[ni][2] + pf[ni][3];
            }
        } else {
            #pragma unroll
            for (int ni = 0; ni < 8; ni++) {
                pf[ni][0] = ex2(pf[ni][0]);
                pf[ni][1] = ex2(pf[ni][1]);
                pf[ni][2] = ex2(pf[ni][2]);
                pf[ni][3] = ex2(pf[ni][3]);
                l0 += pf[ni][0] + pf[ni][1];
                l1 += pf[ni][2] + pf[ni][3];
            }
        }

        // O += P @ V : C-frag packs straight into A-frags, same lane
        #pragma unroll
        for (int kt = 0; kt < 4; kt++) {
            uint32_t a[4];
            a[0] = packh2(pf[2 * kt][0],     pf[2 * kt][1]);
            a[1] = packh2(pf[2 * kt][2],     pf[2 * kt][3]);
            a[2] = packh2(pf[2 * kt + 1][0], pf[2 * kt + 1][1]);
            a[3] = packh2(pf[2 * kt + 1][2], pf[2 * kt + 1][3]);
            const int jp0 = 8 * kt + t;
            #pragma unroll
            for (int ni = 0; ni < 8; ni++) {
                uint32_t bf2[2];
                bf2[0] = Vs[jp0 * 68 + ni * 8 + g];
                bf2[1] = Vs[(jp0 + 4) * 68 + ni * 8 + g];
                mma_f16(oacc[ni], a, bf2);
            }
        }
    }

    // single cross-lane l reduction (rows live on lanes sharing g, t=0..3)
    l0 += __shfl_xor_sync(0xffffffffu, l0, 1);
    l0 += __shfl_xor_sync(0xffffffffu, l0, 2);
    l1 += __shfl_xor_sync(0xffffffffu, l1, 1);
    l1 += __shfl_xor_sync(0xffffffffu, l1, 2);

    const float inv0 = 1.f / l0, inv1 = 1.f / l1;
    const int lr0 = w * 16 + g;
    #pragma unroll
    for (int ni = 0; ni < 8; ni++) {
        const int cc = ni * 8 + 2 * t;
        *(float2*)(O + qbase + (size_t)lr0 * DD + cc) =
            make_float2(oacc[ni][0] * inv0, oacc[ni][1] * inv0);
        *(float2*)(O + qbase + (size_t)(lr0 + 8) * DD + cc) =
            make_float2(oacc[ni][2] * inv1, oacc[ni][3] * inv1);
    }
}

// ---------------------------------------------------------------------------
// Launch
// ---------------------------------------------------------------------------
extern "C" void kernel_launch(void* const* d_in, const int* in_sizes, int n_in,
                              void* d_out, int out_size)
{
    (void)in_sizes; (void)n_in; (void)out_size;

    const float* q     = (const float*)d_in[0];
    const float* kv    = (const float*)d_in[1];
    const float* Wq    = (const float*)d_in[2];
    const float* Wk    = (const float*)d_in[3];
    const float* Wv    = (const float*)d_in[4];
    const float* Wo    = (const float*)d_in[5];
    const float* bo    = (const float*)d_in[6];
    const float* gamma = (const float*)d_in[7];
    const float* beta  = (const float*)d_in[8];
    float* out = (float*)d_out;

    float *qh, *kh, *vh, *attn;
    float2* stats;
    __half* wt;
    cudaGetSymbolAddress((void**)&qh,    g_qh);
    cudaGetSymbolAddress((void**)&kh,    g_kh);
    cudaGetSymbolAddress((void**)&vh,    g_vh);
    cudaGetSymbolAddress((void**)&attn,  g_attn);
    cudaGetSymbolAddress((void**)&stats, g_stats);
    cudaGetSymbolAddress((void**)&wt,    g_wt);

    const __half* wtq = wt;
    const __half* wtk = wt + 1 * DD * DD;
    const __half* wtv = wt + 2 * DD * DD;
    const __half* wto = wt + 3 * DD * DD;

    // Transpose + fp16-convert all weights
    {
        dim3 grid(DD / 32, DD / 32, 4);
        transpose_w<<<grid, dim3(32, 8)>>>(Wq, Wk, Wv, Wo, wt);
    }
    // Q projection: 8192 x 512  (grid 4 x 128 = 512 CTAs)
    {
        dim3 grid(DD / 128, (BB * NQ) / 64, 1);
        gemm_f16<false, false><<<grid, 256>>>(q, wtq, nullptr, nullptr,
                                              nullptr, nullptr, nullptr,
                                              qh, nullptr);
    }
    // K and V projections: 2048 x 512, z selects  (grid 4 x 32 x 2 = 256 CTAs)
    {
        dim3 grid(DD / 128, (BB * NKV) / 64, 2);
        gemm_f16<false, false><<<grid, 256>>>(kv, wtk, wtv, nullptr,
                                              nullptr, nullptr, nullptr,
                                              kh, vh);
    }
    // Attention
    {
        dim3 grid(NQ / 128, HH, BB);
        attn_f16<<<grid, 256>>>(qh, kh, vh, attn);
    }
    // Row stats for fused LayerNorm
    rowstats<<<(BB * NQ) / 8, 256>>>(attn, stats);
    // Output projection with fused LN + bias
    {
        dim3 grid(DD / 128, (BB * NQ) / 64, 1);
        gemm_f16<true, true><<<grid, 256>>>(attn, wto, nullptr, bo,
                                            stats, gamma, beta,
                                            out, nullptr);
    }
}

// round 8
// speedup vs baseline: 1.1851x; 1.1851x over previous
#include <cuda_runtime.h>
#include <cuda_fp16.h>
#include <math_constants.h>
#include <cstdint>
#include <cstddef>

#define BB 2
#define NQ 4096
#define NKV 1024
#define DD 512
#define HH 8
#define DH 64
#define LN_EPS 1e-5f

// ---------------------------------------------------------------------------
// Scratch
// ---------------------------------------------------------------------------
__device__ __half g_qh[BB * NQ * DD];    // (q @ (Wq/8)) fp16
__device__ __half g_kh[BB * NKV * DD];   // kv @ Wk fp16
__device__ __half g_vh[BB * NKV * DD];   // kv @ Wv fp16
__device__ float  g_attn[BB * NQ * DD];
__device__ float  g_norm[BB * NQ * DD];
__device__ __half g_wt[4 * DD * DD];     // W^T fp16, [n][k] k-contiguous

// ---------------------------------------------------------------------------
// helpers
// ---------------------------------------------------------------------------
__device__ __forceinline__ uint32_t packh2(float lo, float hi) {
    uint32_t r;
    asm("cvt.rn.f16x2.f32 %0, %1, %2;" : "=r"(r) : "f"(hi), "f"(lo));
    return r;
}

__device__ __forceinline__ void mma_f16(float d[4], const uint32_t a[4],
                                        const uint32_t b[2]) {
    asm("mma.sync.aligned.m16n8k16.row.col.f32.f16.f16.f32 "
        "{%0,%1,%2,%3},{%4,%5,%6,%7},{%8,%9},{%0,%1,%2,%3};"
        : "+f"(d[0]), "+f"(d[1]), "+f"(d[2]), "+f"(d[3])
        : "r"(a[0]), "r"(a[1]), "r"(a[2]), "r"(a[3]), "r"(b[0]), "r"(b[1]));
}

// ---------------------------------------------------------------------------
// Weight transpose + fp16 convert: Wt[z][n][k] = fp16(W_z[k][n] * scale_z)
// Wq pre-scaled by 1/8 (= DH^-0.5) so attention needs no Q scaling.
// ---------------------------------------------------------------------------
__global__ void __launch_bounds__(256) transpose_w(
    const float* __restrict__ Wq, const float* __restrict__ Wk,
    const float* __restrict__ Wv, const float* __restrict__ Wo,
    __half* __restrict__ Wt)
{
    __shared__ float t[32][33];
    const int z = blockIdx.z;
    const float* W = (z == 0) ? Wq : (z == 1) ? Wk : (z == 2) ? Wv : Wo;
    const float sc = (z == 0) ? 0.125f : 1.0f;
    __half* T = Wt + (size_t)z * DD * DD;
    const int tx = threadIdx.x, ty = threadIdx.y;
    const int kb = blockIdx.x * 32, nb = blockIdx.y * 32;
    #pragma unroll
    for (int j = 0; j < 4; j++)
        t[ty + j * 8][tx] = W[(size_t)(kb + ty + j * 8) * DD + nb + tx] * sc;
    __syncthreads();
    #pragma unroll
    for (int j = 0; j < 4; j++)
        T[(size_t)(nb + ty + j * 8) * DD + kb + tx] =
            __float2half_rn(t[tx][ty + j * 8]);
}

// ---------------------------------------------------------------------------
// Merged projection GEMM (fp16 output): computes Q, K, V projections in one
// launch. BM=128 BN=128 BK=32, 256 threads, warps 4(M)x2(N), tile 32x64.
// blockIdx.y: [0,64) Q-proj rows, [64,80) K-proj, [80,96) V-proj.
// ---------------------------------------------------------------------------
__global__ void __launch_bounds__(256) proj_gemm(
    const float* __restrict__ Aq, const float* __restrict__ Akv,
    const __half* __restrict__ WtQ, const __half* __restrict__ WtK,
    const __half* __restrict__ WtV,
    __half* __restrict__ Cq, __half* __restrict__ Ck, __half* __restrict__ Cv)
{
    __shared__ uint32_t As[128 * 20];
    __shared__ uint32_t Bs[128 * 20];

    const int ty = blockIdx.y;
    const float* __restrict__ A;
    const __half* __restrict__ Wt;
    __half* __restrict__ C;
    int row0;
    if (ty < 64)      { A = Aq;  Wt = WtQ; C = Cq; row0 = ty * 128; }
    else if (ty < 80) { A = Akv; Wt = WtK; C = Ck; row0 = (ty - 64) * 128; }
    else              { A = Akv; Wt = WtV; C = Cv; row0 = (ty - 80) * 128; }

    const int tid = threadIdx.x;
    const int lane = tid & 31;
    const int g = lane >> 2, t = lane & 3;
    const int w = tid >> 5;
    const int wm = w >> 1, wn = w & 1;
    const int col0 = blockIdx.x * 128;

    const int ar = tid >> 3;            // + i*32
    const int af4 = tid & 7;
    const int br = tid >> 2;            // + i*64
    const int bf = tid & 3;

    float4 aR[4];
    uint4 bR[2];

    auto loadA = [&](int k0) {
        #pragma unroll
        for (int i = 0; i < 4; i++)
            aR[i] = *(const float4*)(A + (size_t)(row0 + ar + i * 32) * DD + k0 + af4 * 4);
    };
    auto loadB = [&](int k0) {
        #pragma unroll
        for (int i = 0; i < 2; i++)
            bR[i] = *(const uint4*)(Wt + (size_t)(col0 + br + i * 64) * DD + k0 + bf * 8);
    };

    float acc[2][8][4];
    #pragma unroll
    for (int mi = 0; mi < 2; mi++)
        #pragma unroll
        for (int ni = 0; ni < 8; ni++)
            #pragma unroll
            for (int r = 0; r < 4; r++) acc[mi][ni][r] = 0.f;

    loadA(0);
    loadB(0);

    for (int k0 = 0; k0 < DD; k0 += 32) {
        #pragma unroll
        for (int i = 0; i < 4; i++)
            *(uint2*)&As[(ar + i * 32) * 20 + af4 * 2] =
                make_uint2(packh2(aR[i].x, aR[i].y), packh2(aR[i].z, aR[i].w));
        #pragma unroll
        for (int i = 0; i < 2; i++)
            *(uint4*)&Bs[(br + i * 64) * 20 + bf * 4] = bR[i];
        __syncthreads();

        if (k0 + 32 < DD) { loadA(k0 + 32); loadB(k0 + 32); }

        #pragma unroll
        for (int ks = 0; ks < 2; ks++) {
            const int ko = ks * 8;
            uint32_t af[2][4];
            #pragma unroll
            for (int mi = 0; mi < 2; mi++) {
                const int mb = wm * 32 + mi * 16;
                af[mi][0] = As[(mb + g) * 20 + ko + t];
                af[mi][1] = As[(mb + g + 8) * 20 + ko + t];
                af[mi][2] = As[(mb + g) * 20 + ko + t + 4];
                af[mi][3] = As[(mb + g + 8) * 20 + ko + t + 4];
            }
            #pragma unroll
            for (int ni = 0; ni < 8; ni++) {
                const int nb = wn * 64 + ni * 8;
                uint32_t bf2[2];
                bf2[0] = Bs[(nb + g) * 20 + ko + t];
                bf2[1] = Bs[(nb + g) * 20 + ko + t + 4];
                mma_f16(acc[0][ni], af[0], bf2);
                mma_f16(acc[1][ni], af[1], bf2);
            }
        }
        __syncthreads();
    }

    // fp16 epilogue: pack pairs, 4B stores
    #pragma unroll
    for (int mi = 0; mi < 2; mi++) {
        const int rr0 = row0 + wm * 32 + mi * 16 + g;
        #pragma unroll
        for (int ni = 0; ni < 8; ni++) {
            const int cc = col0 + wn * 64 + ni * 8 + 2 * t;
            *(uint32_t*)(C + (size_t)rr0 * DD + cc) =
                packh2(acc[mi][ni][0], acc[mi][ni][1]);
            *(uint32_t*)(C + (size_t)(rr0 + 8) * DD + cc) =
                packh2(acc[mi][ni][2], acc[mi][ni][3]);
        }
    }
}

// ---------------------------------------------------------------------------
// Output GEMM (fp32 in/out + bias): C = A @ Wo. Round-6 geometry.
// ---------------------------------------------------------------------------
__global__ void __launch_bounds__(256) out_gemm(
    const float* __restrict__ A, const __half* __restrict__ Wt,
    const float* __restrict__ bias, float* __restrict__ C)
{
    __shared__ uint32_t As[128 * 20];
    __shared__ uint32_t Bs[128 * 20];

    const int tid = threadIdx.x;
    const int lane = tid & 31;
    const int g = lane >> 2, t = lane & 3;
    const int w = tid >> 5;
    const int wm = w >> 1, wn = w & 1;
    const int row0 = blockIdx.y * 128, col0 = blockIdx.x * 128;

    const int ar = tid >> 3;
    const int af4 = tid & 7;
    const int br = tid >> 2;
    const int bf = tid & 3;

    float4 aR[4];
    uint4 bR[2];

    auto loadA = [&](int k0) {
        #pragma unroll
        for (int i = 0; i < 4; i++)
            aR[i] = *(const float4*)(A + (size_t)(row0 + ar + i * 32) * DD + k0 + af4 * 4);
    };
    auto loadB = [&](int k0) {
        #pragma unroll
        for (int i = 0; i < 2; i++)
            bR[i] = *(const uint4*)(Wt + (size_t)(col0 + br + i * 64) * DD + k0 + bf * 8);
    };

    float acc[2][8][4];
    #pragma unroll
    for (int mi = 0; mi < 2; mi++)
        #pragma unroll
        for (int ni = 0; ni < 8; ni++)
            #pragma unroll
            for (int r = 0; r < 4; r++) acc[mi][ni][r] = 0.f;

    loadA(0);
    loadB(0);

    for (int k0 = 0; k0 < DD; k0 += 32) {
        #pragma unroll
        for (int i = 0; i < 4; i++)
            *(uint2*)&As[(ar + i * 32) * 20 + af4 * 2] =
                make_uint2(packh2(aR[i].x, aR[i].y), packh2(aR[i].z, aR[i].w));
        #pragma unroll
        for (int i = 0; i < 2; i++)
            *(uint4*)&Bs[(br + i * 64) * 20 + bf * 4] = bR[i];
        __syncthreads();

        if (k0 + 32 < DD) { loadA(k0 + 32); loadB(k0 + 32); }

        #pragma unroll
        for (int ks = 0; ks < 2; ks++) {
            const int ko = ks * 8;
            uint32_t af[2][4];
            #pragma unroll
            for (int mi = 0; mi < 2; mi++) {
                const int mb = wm * 32 + mi * 16;
                af[mi][0] = As[(mb + g) * 20 + ko + t];
                af[mi][1] = As[(mb + g + 8) * 20 + ko + t];
                af[mi][2] = As[(mb + g) * 20 + ko + t + 4];
                af[mi][3] = As[(mb + g + 8) * 20 + ko + t + 4];
            }
            #pragma unroll
            for (int ni = 0; ni < 8; ni++) {
                const int nb = wn * 64 + ni * 8;
                uint32_t bf2[2];
                bf2[0] = Bs[(nb + g) * 20 + ko + t];
                bf2[1] = Bs[(nb + g) * 20 + ko + t + 4];
                mma_f16(acc[0][ni], af[0], bf2);
                mma_f16(acc[1][ni], af[1], bf2);
            }
        }
        __syncthreads();
    }

    #pragma unroll
    for (int mi = 0; mi < 2; mi++) {
        const int rr0 = row0 + wm * 32 + mi * 16 + g;
        #pragma unroll
        for (int ni = 0; ni < 8; ni++) {
            const int cc = col0 + wn * 64 + ni * 8 + 2 * t;
            const float2 bv = *(const float2*)(bias + cc);
            *(float2*)(C + (size_t)rr0 * DD + cc) =
                make_float2(acc[mi][ni][0] + bv.x, acc[mi][ni][1] + bv.y);
            *(float2*)(C + (size_t)(rr0 + 8) * DD + cc) =
                make_float2(acc[mi][ni][2] + bv.x, acc[mi][ni][3] + bv.y);
        }
    }
}

// ---------------------------------------------------------------------------
// Flash attention (round-6 core: online softmax, __expf). Inputs now fp16:
// tile loads are pure 16B copies (K/Q) and PRMT interleave (V). Q pre-scaled
// via Wq. Block = 128 queries x (b,h), 8 warps x 16 rows.
// ---------------------------------------------------------------------------
__global__ void __launch_bounds__(256) attn_f16(
    const __half* __restrict__ Qh, const __half* __restrict__ Kh,
    const __half* __restrict__ Vh, float* __restrict__ O)
{
    __shared__ uint32_t Qs[128 * 36];
    __shared__ uint32_t Ks[64 * 36];
    __shared__ uint32_t Vs[32 * 68];

    const int tile = (NQ / 128 - 1) - blockIdx.x;   // big tiles first
    const int h = blockIdx.y, b = blockIdx.z;
    const int tid = threadIdx.x;
    const int lane = tid & 31;
    const int g = lane >> 2, t = lane & 3;
    const int w = tid >> 5;

    const size_t qbase = ((size_t)b * NQ + (size_t)tile * 128) * DD + (size_t)h * DH;
    const size_t kvbase = (size_t)b * NKV * DD + (size_t)h * DH;

    // Q tile: direct fp16 copy, 128 rows x 8 uint4 = 1024 units, 4/thread
    #pragma unroll
    for (int i = 0; i < 4; i++) {
        const int idx = tid + i * 256;
        const int r = idx >> 3, c = idx & 7;
        const uint4 u = *(const uint4*)(Qh + qbase + (size_t)r * DD + c * 8);
        *(uint4*)&Qs[r * 36 + c * 4] = u;
    }

    float oacc[8][4];
    #pragma unroll
    for (int ni = 0; ni < 8; ni++)
        #pragma unroll
        for (int r = 0; r < 4; r++) oacc[ni][r] = 0.f;
    float m0 = -CUDART_INF_F, m1 = -CUDART_INF_F, l0 = 0.f, l1 = 0.f;

    const int row0 = tile * 128 + w * 16 + g;
    const int lim0 = row0 >> 2;
    const int lim1 = (row0 + 8) >> 2;
    const int nch = (32 * tile + 95) >> 6;

    for (int c = 0; c < nch; c++) {
        const int k0 = c * 64;
        __syncthreads();    // protect Ks/Vs from previous readers

        // K tile: direct fp16 copy, 64 rows x 8 uint4 = 512 units, 2/thread
        #pragma unroll
        for (int i = 0; i < 2; i++) {
            const int idx = tid + i * 256;
            const int r = idx >> 3, cc = idx & 7;
            const uint4 u = *(const uint4*)(Kh + kvbase + (size_t)(k0 + r) * DD + cc * 8);
            *(uint4*)&Ks[r * 36 + cc * 4] = u;
        }
        // V tile: fp16 loads + PRMT pair-interleave
        #pragma unroll
        for (int i = 0; i < 2; i++) {
            const int idx = tid + i * 256;
            const int jp = idx >> 4, d4 = idx & 15;
            const uint2 va = *(const uint2*)(Vh + kvbase + (size_t)(k0 + 2 * jp) * DD + d4 * 4);
            const uint2 vb = *(const uint2*)(Vh + kvbase + (size_t)(k0 + 2 * jp + 1) * DD + d4 * 4);
            uint4 u;
            u.x = __byte_perm(va.x, vb.x, 0x5410);
            u.y = __byte_perm(va.x, vb.x, 0x7632);
            u.z = __byte_perm(va.y, vb.y, 0x5410);
            u.w = __byte_perm(va.y, vb.y, 0x7632);
            *(uint4*)&Vs[jp * 68 + d4 * 4] = u;
        }
        __syncthreads();

        // S = Q @ K^T
        float pf[8][4];
        #pragma unroll
        for (int ni = 0; ni < 8; ni++)
            #pragma unroll
            for (int r = 0; r < 4; r++) pf[ni][r] = 0.f;

        const int mb = w * 16;
        #pragma unroll
        for (int kt = 0; kt < 4; kt++) {
            const int ko = kt * 8;
            uint32_t af[4];
            af[0] = Qs[(mb + g) * 36 + ko + t];
            af[1] = Qs[(mb + g + 8) * 36 + ko + t];
            af[2] = Qs[(mb + g) * 36 + ko + t + 4];
            af[3] = Qs[(mb + g + 8) * 36 + ko + t + 4];
            #pragma unroll
            for (int ni = 0; ni < 8; ni++) {
                uint32_t bf2[2];
                bf2[0] = Ks[(ni * 8 + g) * 36 + ko + t];
                bf2[1] = Ks[(ni * 8 + g) * 36 + ko + t + 4];
                mma_f16(pf[ni], af, bf2);
            }
        }

        // mask (diagonal chunk only) + online softmax
        if (c == nch - 1) {
            #pragma unroll
            for (int ni = 0; ni < 8; ni++) {
                const int j = k0 + ni * 8 + 2 * t;
                if (j > lim0)     pf[ni][0] = -CUDART_INF_F;
                if (j + 1 > lim0) pf[ni][1] = -CUDART_INF_F;
                if (j > lim1)     pf[ni][2] = -CUDART_INF_F;
                if (j + 1 > lim1) pf[ni][3] = -CUDART_INF_F;
            }
        }

        float mx0 = -CUDART_INF_F, mx1 = -CUDART_INF_F;
        #pragma unroll
        for (int ni = 0; ni < 8; ni++) {
            mx0 = fmaxf(mx0, fmaxf(pf[ni][0], pf[ni][1]));
            mx1 = fmaxf(mx1, fmaxf(pf[ni][2], pf[ni][3]));
        }
        mx0 = fmaxf(mx0, __shfl_xor_sync(0xffffffffu, mx0, 1));
        mx0 = fmaxf(mx0, __shfl_xor_sync(0xffffffffu, mx0, 2));
        mx1 = fmaxf(mx1, __shfl_xor_sync(0xffffffffu, mx1, 1));
        mx1 = fmaxf(mx1, __shfl_xor_sync(0xffffffffu, mx1, 2));

        const float mn0 = fmaxf(m0, mx0), mn1 = fmaxf(m1, mx1);
        const float al0 = __expf(m0 - mn0), al1 = __expf(m1 - mn1);
        m0 = mn0; m1 = mn1;

        float rs0 = 0.f, rs1 = 0.f;
        #pragma unroll
        for (int ni = 0; ni < 8; ni++) {
            pf[ni][0] = __expf(pf[ni][0] - mn0);
            pf[ni][1] = __expf(pf[ni][1] - mn0);
            pf[ni][2] = __expf(pf[ni][2] - mn1);
            pf[ni][3] = __expf(pf[ni][3] - mn1);
            rs0 += pf[ni][0] + pf[ni][1];
            rs1 += pf[ni][2] + pf[ni][3];
        }
        rs0 += __shfl_xor_sync(0xffffffffu, rs0, 1);
        rs0 += __shfl_xor_sync(0xffffffffu, rs0, 2);
        rs1 += __shfl_xor_sync(0xffffffffu, rs1, 1);
        rs1 += __shfl_xor_sync(0xffffffffu, rs1, 2);
        l0 = l0 * al0 + rs0;
        l1 = l1 * al1 + rs1;

        #pragma unroll
        for (int ni = 0; ni < 8; ni++) {
            oacc[ni][0] *= al0; oacc[ni][1] *= al0;
            oacc[ni][2] *= al1; oacc[ni][3] *= al1;
        }

        // O += P @ V : C-frag packs straight into A-frags, same lane
        #pragma unroll
        for (int kt = 0; kt < 4; kt++) {
            uint32_t a[4];
            a[0] = packh2(pf[2 * kt][0],     pf[2 * kt][1]);
            a[1] = packh2(pf[2 * kt][2],     pf[2 * kt][3]);
            a[2] = packh2(pf[2 * kt + 1][0], pf[2 * kt + 1][1]);
            a[3] = packh2(pf[2 * kt + 1][2], pf[2 * kt + 1][3]);
            const int jp0 = 8 * kt + t;
            #pragma unroll
            for (int ni = 0; ni < 8; ni++) {
                uint32_t bf2[2];
                bf2[0] = Vs[jp0 * 68 + ni * 8 + g];
                bf2[1] = Vs[(jp0 + 4) * 68 + ni * 8 + g];
                mma_f16(oacc[ni], a, bf2);
            }
        }
    }

    const float inv0 = 1.f / l0, inv1 = 1.f / l1;
    const int lr0 = w * 16 + g;
    #pragma unroll
    for (int ni = 0; ni < 8; ni++) {
        const int cc = ni * 8 + 2 * t;
        *(float2*)(O + qbase + (size_t)lr0 * DD + cc) =
            make_float2(oacc[ni][0] * inv0, oacc[ni][1] * inv0);
        *(float2*)(O + qbase + (size_t)(lr0 + 8) * DD + cc) =
            make_float2(oacc[ni][2] * inv1, oacc[ni][3] * inv1);
    }
}

// ---------------------------------------------------------------------------
// LayerNorm over last dim (512). One block per row. (round-6)
// ---------------------------------------------------------------------------
__global__ void __launch_bounds__(256) ln_kernel(
    const float* __restrict__ X, const float* __restrict__ gamma,
    const float* __restrict__ beta, float* __restrict__ Y)
{
    __shared__ float red[16];
    __shared__ float mv[2];

    const int row = blockIdx.x;
    const int tid = threadIdx.x;
    const float* x = X + (size_t)row * DD;

    const float2 v = *(const float2*)(x + tid * 2);
    float s = v.x + v.y;
    float sq = v.x * v.x + v.y * v.y;

    #pragma unroll
    for (int off = 16; off > 0; off >>= 1) {
        s += __shfl_xor_sync(0xffffffffu, s, off);
        sq += __shfl_xor_sync(0xffffffffu, sq, off);
    }
    const int wid = tid >> 5;
    if ((tid & 31) == 0) { red[wid] = s; red[8 + wid] = sq; }
    __syncthreads();
    if (tid == 0) {
        float S = 0.f, SQ = 0.f;
        #pragma unroll
        for (int ww = 0; ww < 8; ww++) { S += red[ww]; SQ += red[8 + ww]; }
        const float mean = S * (1.f / DD);
        const float var = SQ * (1.f / DD) - mean * mean;
        mv[0] = mean;
        mv[1] = rsqrtf(var + LN_EPS);
    }
    __syncthreads();
    const float mean = mv[0], r = mv[1];

    const float2 gm = *(const float2*)(gamma + tid * 2);
    const float2 be = *(const float2*)(beta + tid * 2);
    float2 out;
    out.x = (v.x - mean) * r * gm.x + be.x;
    out.y = (v.y - mean) * r * gm.y + be.y;
    *(float2*)(Y + (size_t)row * DD + tid * 2) = out;
}

// ---------------------------------------------------------------------------
// Launch
// ---------------------------------------------------------------------------
extern "C" void kernel_launch(void* const* d_in, const int* in_sizes, int n_in,
                              void* d_out, int out_size)
{
    (void)in_sizes; (void)n_in; (void)out_size;

    const float* q     = (const float*)d_in[0];
    const float* kv    = (const float*)d_in[1];
    const float* Wq    = (const float*)d_in[2];
    const float* Wk    = (const float*)d_in[3];
    const float* Wv    = (const float*)d_in[4];
    const float* Wo    = (const float*)d_in[5];
    const float* bo    = (const float*)d_in[6];
    const float* gamma = (const float*)d_in[7];
    const float* beta  = (const float*)d_in[8];
    float* out = (float*)d_out;

    __half *qh, *kh, *vh, *wt;
    float *attn, *norm;
    cudaGetSymbolAddress((void**)&qh,   g_qh);
    cudaGetSymbolAddress((void**)&kh,   g_kh);
    cudaGetSymbolAddress((void**)&vh,   g_vh);
    cudaGetSymbolAddress((void**)&attn, g_attn);
    cudaGetSymbolAddress((void**)&norm, g_norm);
    cudaGetSymbolAddress((void**)&wt,   g_wt);

    const __half* wtq = wt;
    const __half* wtk = wt + 1 * DD * DD;
    const __half* wtv = wt + 2 * DD * DD;
    const __half* wto = wt + 3 * DD * DD;

    // Transpose + fp16-convert all weights (Wq pre-scaled by 1/8)
    {
        dim3 grid(DD / 32, DD / 32, 4);
        transpose_w<<<grid, dim3(32, 8)>>>(Wq, Wk, Wv, Wo, wt);
    }
    // All three projections in one launch: y in [0,64) Q, [64,80) K, [80,96) V
    {
        dim3 grid(DD / 128, 96, 1);
        proj_gemm<<<grid, 256>>>(q, kv, wtq, wtk, wtv, qh, kh, vh);
    }
    // Attention
    {
        dim3 grid(NQ / 128, HH, BB);
        attn_f16<<<grid, 256>>>(qh, kh, vh, attn);
    }
    // LayerNorm
    ln_kernel<<<BB * NQ, 256>>>(attn, gamma, beta, norm);
    // Output projection + bias
    {
        dim3 grid(DD / 128, (BB * NQ) / 128, 1);
        out_gemm<<<grid, 256>>>(norm, wto, bo, out);
    }
}

// round 9
// speedup vs baseline: 1.2676x; 1.0696x over previous
#include <cuda_runtime.h>
#include <cuda_fp16.h>
#include <math_constants.h>
#include <cstdint>
#include <cstddef>

#define BB 2
#define NQ 4096
#define NKV 1024
#define DD 512
#define HH 8
#define DH 64
#define LN_EPS 1e-5f

// ---------------------------------------------------------------------------
// Scratch
// ---------------------------------------------------------------------------
__device__ __half g_qh[BB * NQ * DD];    // (q @ (Wq/8)) fp16
__device__ __half g_kh[BB * NKV * DD];   // kv @ Wk fp16
__device__ __half g_vh[BB * NKV * DD];   // kv @ Wv fp16
__device__ float  g_attn[BB * NQ * DD];
__device__ float2 g_stats[BB * NQ];      // per-row (mean, rstd)
__device__ __half g_wt[4 * DD * DD];     // W^T fp16, [n][k] k-contiguous

// ---------------------------------------------------------------------------
// helpers
// ---------------------------------------------------------------------------
__device__ __forceinline__ uint32_t packh2(float lo, float hi) {
    uint32_t r;
    asm("cvt.rn.f16x2.f32 %0, %1, %2;" : "=r"(r) : "f"(hi), "f"(lo));
    return r;
}

__device__ __forceinline__ void mma_f16(float d[4], const uint32_t a[4],
                                        const uint32_t b[2]) {
    asm("mma.sync.aligned.m16n8k16.row.col.f32.f16.f16.f32 "
        "{%0,%1,%2,%3},{%4,%5,%6,%7},{%8,%9},{%0,%1,%2,%3};"
        : "+f"(d[0]), "+f"(d[1]), "+f"(d[2]), "+f"(d[3])
        : "r"(a[0]), "r"(a[1]), "r"(a[2]), "r"(a[3]), "r"(b[0]), "r"(b[1]));
}

// ---------------------------------------------------------------------------
// Weight transpose + fp16 convert: Wt[z][n][k] = fp16(W_z[k][n] * scale_z)
// Wq pre-scaled by 1/8 (= DH^-0.5).
// ---------------------------------------------------------------------------
__global__ void __launch_bounds__(256) transpose_w(
    const float* __restrict__ Wq, const float* __restrict__ Wk,
    const float* __restrict__ Wv, const float* __restrict__ Wo,
    __half* __restrict__ Wt)
{
    __shared__ float t[32][33];
    const int z = blockIdx.z;
    const float* W = (z == 0) ? Wq : (z == 1) ? Wk : (z == 2) ? Wv : Wo;
    const float sc = (z == 0) ? 0.125f : 1.0f;
    __half* T = Wt + (size_t)z * DD * DD;
    const int tx = threadIdx.x, ty = threadIdx.y;
    const int kb = blockIdx.x * 32, nb = blockIdx.y * 32;
    #pragma unroll
    for (int j = 0; j < 4; j++)
        t[ty + j * 8][tx] = W[(size_t)(kb + ty + j * 8) * DD + nb + tx] * sc;
    __syncthreads();
    #pragma unroll
    for (int j = 0; j < 4; j++)
        T[(size_t)(nb + ty + j * 8) * DD + kb + tx] =
            __float2half_rn(t[tx][ty + j * 8]);
}

// ---------------------------------------------------------------------------
// Row stats for LN fusion: one warp per row of X[*, 512]
// ---------------------------------------------------------------------------
__global__ void __launch_bounds__(256) rowstats(
    const float* __restrict__ X, float2* __restrict__ st)
{
    const int w = threadIdx.x >> 5, lane = threadIdx.x & 31;
    const int row = blockIdx.x * 8 + w;
    const float* x = X + (size_t)row * DD;
    float s = 0.f, sq = 0.f;
    #pragma unroll
    for (int j = 0; j < 4; j++) {
        const float4 v = *(const float4*)(x + lane * 4 + j * 128);
        s += v.x + v.y + v.z + v.w;
        sq += v.x * v.x + v.y * v.y + v.z * v.z + v.w * v.w;
    }
    #pragma unroll
    for (int off = 16; off > 0; off >>= 1) {
        s += __shfl_xor_sync(0xffffffffu, s, off);
        sq += __shfl_xor_sync(0xffffffffu, sq, off);
    }
    if (lane == 0) {
        const float mean = s * (1.f / DD);
        const float var = sq * (1.f / DD) - mean * mean;
        st[row] = make_float2(mean, rsqrtf(var + LN_EPS));
    }
}

// ---------------------------------------------------------------------------
// Merged projection GEMM (fp16 output). BM=128 BN=128 BK=32, 256 threads,
// warps 4(M)x2(N), tile 32x64. blockIdx.y: [0,64) Q, [64,80) K, [80,96) V.
// ---------------------------------------------------------------------------
__global__ void __launch_bounds__(256) proj_gemm(
    const float* __restrict__ Aq, const float* __restrict__ Akv,
    const __half* __restrict__ WtQ, const __half* __restrict__ WtK,
    const __half* __restrict__ WtV,
    __half* __restrict__ Cq, __half* __restrict__ Ck, __half* __restrict__ Cv)
{
    __shared__ uint32_t As[128 * 20];
    __shared__ uint32_t Bs[128 * 20];

    const int ty = blockIdx.y;
    const float* __restrict__ A;
    const __half* __restrict__ Wt;
    __half* __restrict__ C;
    int row0;
    if (ty < 64)      { A = Aq;  Wt = WtQ; C = Cq; row0 = ty * 128; }
    else if (ty < 80) { A = Akv; Wt = WtK; C = Ck; row0 = (ty - 64) * 128; }
    else              { A = Akv; Wt = WtV; C = Cv; row0 = (ty - 80) * 128; }

    const int tid = threadIdx.x;
    const int lane = tid & 31;
    const int g = lane >> 2, t = lane & 3;
    const int w = tid >> 5;
    const int wm = w >> 1, wn = w & 1;
    const int col0 = blockIdx.x * 128;

    const int ar = tid >> 3;
    const int af4 = tid & 7;
    const int br = tid >> 2;
    const int bf = tid & 3;

    float4 aR[4];
    uint4 bR[2];

    auto loadA = [&](int k0) {
        #pragma unroll
        for (int i = 0; i < 4; i++)
            aR[i] = *(const float4*)(A + (size_t)(row0 + ar + i * 32) * DD + k0 + af4 * 4);
    };
    auto loadB = [&](int k0) {
        #pragma unroll
        for (int i = 0; i < 2; i++)
            bR[i] = *(const uint4*)(Wt + (size_t)(col0 + br + i * 64) * DD + k0 + bf * 8);
    };

    float acc[2][8][4];
    #pragma unroll
    for (int mi = 0; mi < 2; mi++)
        #pragma unroll
        for (int ni = 0; ni < 8; ni++)
            #pragma unroll
            for (int r = 0; r < 4; r++) acc[mi][ni][r] = 0.f;

    loadA(0);
    loadB(0);

    for (int k0 = 0; k0 < DD; k0 += 32) {
        #pragma unroll
        for (int i = 0; i < 4; i++)
            *(uint2*)&As[(ar + i * 32) * 20 + af4 * 2] =
                make_uint2(packh2(aR[i].x, aR[i].y), packh2(aR[i].z, aR[i].w));
        #pragma unroll
        for (int i = 0; i < 2; i++)
            *(uint4*)&Bs[(br + i * 64) * 20 + bf * 4] = bR[i];
        __syncthreads();

        if (k0 + 32 < DD) { loadA(k0 + 32); loadB(k0 + 32); }

        #pragma unroll
        for (int ks = 0; ks < 2; ks++) {
            const int ko = ks * 8;
            uint32_t af[2][4];
            #pragma unroll
            for (int mi = 0; mi < 2; mi++) {
                const int mb = wm * 32 + mi * 16;
                af[mi][0] = As[(mb + g) * 20 + ko + t];
                af[mi][1] = As[(mb + g + 8) * 20 + ko + t];
                af[mi][2] = As[(mb + g) * 20 + ko + t + 4];
                af[mi][3] = As[(mb + g + 8) * 20 + ko + t + 4];
            }
            #pragma unroll
            for (int ni = 0; ni < 8; ni++) {
                const int nb = wn * 64 + ni * 8;
                uint32_t bf2[2];
                bf2[0] = Bs[(nb + g) * 20 + ko + t];
                bf2[1] = Bs[(nb + g) * 20 + ko + t + 4];
                mma_f16(acc[0][ni], af[0], bf2);
                mma_f16(acc[1][ni], af[1], bf2);
            }
        }
        __syncthreads();
    }

    #pragma unroll
    for (int mi = 0; mi < 2; mi++) {
        const int rr0 = row0 + wm * 32 + mi * 16 + g;
        #pragma unroll
        for (int ni = 0; ni < 8; ni++) {
            const int cc = col0 + wn * 64 + ni * 8 + 2 * t;
            *(uint32_t*)(C + (size_t)rr0 * DD + cc) =
                packh2(acc[mi][ni][0], acc[mi][ni][1]);
            *(uint32_t*)(C + (size_t)(rr0 + 8) * DD + cc) =
                packh2(acc[mi][ni][2], acc[mi][ni][3]);
        }
    }
}

// ---------------------------------------------------------------------------
// Output GEMM with fused LayerNorm: C = LN(A)@Wo + bias. BM=128 (proven
// geometry); LN affine applied in the fp32 A-loader using precomputed stats.
// ---------------------------------------------------------------------------
__global__ void __launch_bounds__(256) out_gemm(
    const float* __restrict__ A, const __half* __restrict__ Wt,
    const float* __restrict__ bias, const float2* __restrict__ stats,
    const float* __restrict__ gamma, const float* __restrict__ beta,
    float* __restrict__ C)
{
    __shared__ uint32_t As[128 * 20];
    __shared__ uint32_t Bs[128 * 20];

    const int tid = threadIdx.x;
    const int lane = tid & 31;
    const int g = lane >> 2, t = lane & 3;
    const int w = tid >> 5;
    const int wm = w >> 1, wn = w & 1;
    const int row0 = blockIdx.y * 128, col0 = blockIdx.x * 128;

    const int ar = tid >> 3;
    const int af4 = tid & 7;
    const int br = tid >> 2;
    const int bf = tid & 3;

    float a_sc[4], a_sh[4];
    #pragma unroll
    for (int i = 0; i < 4; i++) {
        const float2 st = stats[row0 + ar + i * 32];
        a_sc[i] = st.y;
        a_sh[i] = -st.x * st.y;
    }

    float4 aR[4];
    uint4 bR[2];

    auto loadA = [&](int k0) {
        #pragma unroll
        for (int i = 0; i < 4; i++)
            aR[i] = *(const float4*)(A + (size_t)(row0 + ar + i * 32) * DD + k0 + af4 * 4);
    };
    auto loadB = [&](int k0) {
        #pragma unroll
        for (int i = 0; i < 2; i++)
            bR[i] = *(const uint4*)(Wt + (size_t)(col0 + br + i * 64) * DD + k0 + bf * 8);
    };

    float acc[2][8][4];
    #pragma unroll
    for (int mi = 0; mi < 2; mi++)
        #pragma unroll
        for (int ni = 0; ni < 8; ni++)
            #pragma unroll
            for (int r = 0; r < 4; r++) acc[mi][ni][r] = 0.f;

    loadA(0);
    loadB(0);

    for (int k0 = 0; k0 < DD; k0 += 32) {
        const float4 g4 = *(const float4*)(gamma + k0 + af4 * 4);
        const float4 b4 = *(const float4*)(beta + k0 + af4 * 4);
        #pragma unroll
        for (int i = 0; i < 4; i++) {
            float4 v = aR[i];
            v.x = fmaf(fmaf(v.x, a_sc[i], a_sh[i]), g4.x, b4.x);
            v.y = fmaf(fmaf(v.y, a_sc[i], a_sh[i]), g4.y, b4.y);
            v.z = fmaf(fmaf(v.z, a_sc[i], a_sh[i]), g4.z, b4.z);
            v.w = fmaf(fmaf(v.w, a_sc[i], a_sh[i]), g4.w, b4.w);
            *(uint2*)&As[(ar + i * 32) * 20 + af4 * 2] =
                make_uint2(packh2(v.x, v.y), packh2(v.z, v.w));
        }
        #pragma unroll
        for (int i = 0; i < 2; i++)
            *(uint4*)&Bs[(br + i * 64) * 20 + bf * 4] = bR[i];
        __syncthreads();

        if (k0 + 32 < DD) { loadA(k0 + 32); loadB(k0 + 32); }

        #pragma unroll
        for (int ks = 0; ks < 2; ks++) {
            const int ko = ks * 8;
            uint32_t af[2][4];
            #pragma unroll
            for (int mi = 0; mi < 2; mi++) {
                const int mb = wm * 32 + mi * 16;
                af[mi][0] = As[(mb + g) * 20 + ko + t];
                af[mi][1] = As[(mb + g + 8) * 20 + ko + t];
                af[mi][2] = As[(mb + g) * 20 + ko + t + 4];
                af[mi][3] = As[(mb + g + 8) * 20 + ko + t + 4];
            }
            #pragma unroll
            for (int ni = 0; ni < 8; ni++) {
                const int nb = wn * 64 + ni * 8;
                uint32_t bf2[2];
                bf2[0] = Bs[(nb + g) * 20 + ko + t];
                bf2[1] = Bs[(nb + g) * 20 + ko + t + 4];
                mma_f16(acc[0][ni], af[0], bf2);
                mma_f16(acc[1][ni], af[1], bf2);
            }
        }
        __syncthreads();
    }

    #pragma unroll
    for (int mi = 0; mi < 2; mi++) {
        const int rr0 = row0 + wm * 32 + mi * 16 + g;
        #pragma unroll
        for (int ni = 0; ni < 8; ni++) {
            const int cc = col0 + wn * 64 + ni * 8 + 2 * t;
            const float2 bv = *(const float2*)(bias + cc);
            *(float2*)(C + (size_t)rr0 * DD + cc) =
                make_float2(acc[mi][ni][0] + bv.x, acc[mi][ni][1] + bv.y);
            *(float2*)(C + (size_t)(rr0 + 8) * DD + cc) =
                make_float2(acc[mi][ni][2] + bv.x, acc[mi][ni][3] + bv.y);
        }
    }
}

// ---------------------------------------------------------------------------
// Flash attention (round-8 core) + register-prefetch pipeline: next chunk's
// K/V LDGs issue right after this chunk's smem stores, overlapping gmem
// latency with MMA/softmax compute.
// ---------------------------------------------------------------------------
__global__ void __launch_bounds__(256) attn_f16(
    const __half* __restrict__ Qh, const __half* __restrict__ Kh,
    const __half* __restrict__ Vh, float* __restrict__ O)
{
    __shared__ uint32_t Qs[128 * 36];
    __shared__ uint32_t Ks[64 * 36];
    __shared__ uint32_t Vs[32 * 68];

    const int tile = (NQ / 128 - 1) - blockIdx.x;   // big tiles first
    const int h = blockIdx.y, b = blockIdx.z;
    const int tid = threadIdx.x;
    const int lane = tid & 31;
    const int g = lane >> 2, t = lane & 3;
    const int w = tid >> 5;

    const size_t qbase = ((size_t)b * NQ + (size_t)tile * 128) * DD + (size_t)h * DH;
    const size_t kvbase = (size_t)b * NKV * DD + (size_t)h * DH;

    // Q tile: direct fp16 copy
    #pragma unroll
    for (int i = 0; i < 4; i++) {
        const int idx = tid + i * 256;
        const int r = idx >> 3, c = idx & 7;
        const uint4 u = *(const uint4*)(Qh + qbase + (size_t)r * DD + c * 8);
        *(uint4*)&Qs[r * 36 + c * 4] = u;
    }

    float oacc[8][4];
    #pragma unroll
    for (int ni = 0; ni < 8; ni++)
        #pragma unroll
        for (int r = 0; r < 4; r++) oacc[ni][r] = 0.f;
    float m0 = -CUDART_INF_F, m1 = -CUDART_INF_F, l0 = 0.f, l1 = 0.f;

    const int row0 = tile * 128 + w * 16 + g;
    const int lim0 = row0 >> 2;
    const int lim1 = (row0 + 8) >> 2;
    const int nch = (32 * tile + 95) >> 6;

    // prefetch registers + geometry
    const int kr8 = tid >> 3, kc8 = tid & 7;
    const int vjp = tid >> 4, vd4 = tid & 15;
    uint4 kR[2];
    uint2 vaR[2], vbR[2];

    auto loadKV = [&](int k0) {
        #pragma unroll
        for (int i = 0; i < 2; i++)
            kR[i] = *(const uint4*)(Kh + kvbase + (size_t)(k0 + kr8 + i * 32) * DD + kc8 * 8);
        #pragma unroll
        for (int i = 0; i < 2; i++) {
            const int jp = vjp + i * 16;
            vaR[i] = *(const uint2*)(Vh + kvbase + (size_t)(k0 + 2 * jp) * DD + vd4 * 4);
            vbR[i] = *(const uint2*)(Vh + kvbase + (size_t)(k0 + 2 * jp + 1) * DD + vd4 * 4);
        }
    };
    auto storeKV = [&]() {
        #pragma unroll
        for (int i = 0; i < 2; i++)
            *(uint4*)&Ks[(kr8 + i * 32) * 36 + kc8 * 4] = kR[i];
        #pragma unroll
        for (int i = 0; i < 2; i++) {
            uint4 u;
            u.x = __byte_perm(vaR[i].x, vbR[i].x, 0x5410);
            u.y = __byte_perm(vaR[i].x, vbR[i].x, 0x7632);
            u.z = __byte_perm(vaR[i].y, vbR[i].y, 0x5410);
            u.w = __byte_perm(vaR[i].y, vbR[i].y, 0x7632);
            *(uint4*)&Vs[(vjp + i * 16) * 68 + vd4 * 4] = u;
        }
    };

    loadKV(0);

    for (int c = 0; c < nch; c++) {
        const int k0 = c * 64;
        __syncthreads();    // smem free (previous chunk's readers done)
        storeKV();
        __syncthreads();
        if (c + 1 < nch) loadKV(k0 + 64);   // overlap with compute below

        // S = Q @ K^T
        float pf[8][4];
        #pragma unroll
        for (int ni = 0; ni < 8; ni++)
            #pragma unroll
            for (int r = 0; r < 4; r++) pf[ni][r] = 0.f;

        const int mb = w * 16;
        #pragma unroll
        for (int kt = 0; kt < 4; kt++) {
            const int ko = kt * 8;
            uint32_t af[4];
            af[0] = Qs[(mb + g) * 36 + ko + t];
            af[1] = Qs[(mb + g + 8) * 36 + ko + t];
            af[2] = Qs[(mb + g) * 36 + ko + t + 4];
            af[3] = Qs[(mb + g + 8) * 36 + ko + t + 4];
            #pragma unroll
            for (int ni = 0; ni < 8; ni++) {
                uint32_t bf2[2];
                bf2[0] = Ks[(ni * 8 + g) * 36 + ko + t];
                bf2[1] = Ks[(ni * 8 + g) * 36 + ko + t + 4];
                mma_f16(pf[ni], af, bf2);
            }
        }

        // mask (diagonal chunk only) + online softmax
        if (c == nch - 1) {
            #pragma unroll
            for (int ni = 0; ni < 8; ni++) {
                const int j = k0 + ni * 8 + 2 * t;
                if (j > lim0)     pf[ni][0] = -CUDART_INF_F;
                if (j + 1 > lim0) pf[ni][1] = -CUDART_INF_F;
                if (j > lim1)     pf[ni][2] = -CUDART_INF_F;
                if (j + 1 > lim1) pf[ni][3] = -CUDART_INF_F;
            }
        }

        float mx0 = -CUDART_INF_F, mx1 = -CUDART_INF_F;
        #pragma unroll
        for (int ni = 0; ni < 8; ni++) {
            mx0 = fmaxf(mx0, fmaxf(pf[ni][0], pf[ni][1]));
            mx1 = fmaxf(mx1, fmaxf(pf[ni][2], pf[ni][3]));
        }
        mx0 = fmaxf(mx0, __shfl_xor_sync(0xffffffffu, mx0, 1));
        mx0 = fmaxf(mx0, __shfl_xor_sync(0xffffffffu, mx0, 2));
        mx1 = fmaxf(mx1, __shfl_xor_sync(0xffffffffu, mx1, 1));
        mx1 = fmaxf(mx1, __shfl_xor_sync(0xffffffffu, mx1, 2));

        const float mn0 = fmaxf(m0, mx0), mn1 = fmaxf(m1, mx1);
        const float al0 = __expf(m0 - mn0), al1 = __expf(m1 - mn1);
        m0 = mn0; m1 = mn1;

        float rs0 = 0.f, rs1 = 0.f;
        #pragma unroll
        for (int ni = 0; ni < 8; ni++) {
            pf[ni][0] = __expf(pf[ni][0] - mn0);
            pf[ni][1] = __expf(pf[ni][1] - mn0);
            pf[ni][2] = __expf(pf[ni][2] - mn1);
            pf[ni][3] = __expf(pf[ni][3] - mn1);
            rs0 += pf[ni][0] + pf[ni][1];
            rs1 += pf[ni][2] + pf[ni][3];
        }
        rs0 += __shfl_xor_sync(0xffffffffu, rs0, 1);
        rs0 += __shfl_xor_sync(0xffffffffu, rs0, 2);
        rs1 += __shfl_xor_sync(0xffffffffu, rs1, 1);
        rs1 += __shfl_xor_sync(0xffffffffu, rs1, 2);
        l0 = l0 * al0 + rs0;
        l1 = l1 * al1 + rs1;

        #pragma unroll
        for (int ni = 0; ni < 8; ni++) {
            oacc[ni][0] *= al0; oacc[ni][1] *= al0;
            oacc[ni][2] *= al1; oacc[ni][3] *= al1;
        }

        // O += P @ V : C-frag packs straight into A-frags, same lane
        #pragma unroll
        for (int kt = 0; kt < 4; kt++) {
            uint32_t a[4];
            a[0] = packh2(pf[2 * kt][0],     pf[2 * kt][1]);
            a[1] = packh2(pf[2 * kt][2],     pf[2 * kt][3]);
            a[2] = packh2(pf[2 * kt + 1][0], pf[2 * kt + 1][1]);
            a[3] = packh2(pf[2 * kt + 1][2], pf[2 * kt + 1][3]);
            const int jp0 = 8 * kt + t;
            #pragma unroll
            for (int ni = 0; ni < 8; ni++) {
                uint32_t bf2[2];
                bf2[0] = Vs[jp0 * 68 + ni * 8 + g];
                bf2[1] = Vs[(jp0 + 4) * 68 + ni * 8 + g];
                mma_f16(oacc[ni], a, bf2);
            }
        }
    }

    const float inv0 = 1.f / l0, inv1 = 1.f / l1;
    const int lr0 = w * 16 + g;
    #pragma unroll
    for (int ni = 0; ni < 8; ni++) {
        const int cc = ni * 8 + 2 * t;
        *(float2*)(O + qbase + (size_t)lr0 * DD + cc) =
            make_float2(oacc[ni][0] * inv0, oacc[ni][1] * inv0);
        *(float2*)(O + qbase + (size_t)(lr0 + 8) * DD + cc) =
            make_float2(oacc[ni][2] * inv1, oacc[ni][3] * inv1);
    }
}

// ---------------------------------------------------------------------------
// Launch
// ---------------------------------------------------------------------------
extern "C" void kernel_launch(void* const* d_in, const int* in_sizes, int n_in,
                              void* d_out, int out_size)
{
    (void)in_sizes; (void)n_in; (void)out_size;

    const float* q     = (const float*)d_in[0];
    const float* kv    = (const float*)d_in[1];
    const float* Wq    = (const float*)d_in[2];
    const float* Wk    = (const float*)d_in[3];
    const float* Wv    = (const float*)d_in[4];
    const float* Wo    = (const float*)d_in[5];
    const float* bo    = (const float*)d_in[6];
    const float* gamma = (const float*)d_in[7];
    const float* beta  = (const float*)d_in[8];
    float* out = (float*)d_out;

    __half *qh, *kh, *vh, *wt;
    float *attn;
    float2 *stats;
    cudaGetSymbolAddress((void**)&qh,    g_qh);
    cudaGetSymbolAddress((void**)&kh,    g_kh);
    cudaGetSymbolAddress((void**)&vh,    g_vh);
    cudaGetSymbolAddress((void**)&attn,  g_attn);
    cudaGetSymbolAddress((void**)&stats, g_stats);
    cudaGetSymbolAddress((void**)&wt,    g_wt);

    const __half* wtq = wt;
    const __half* wtk = wt + 1 * DD * DD;
    const __half* wtv = wt + 2 * DD * DD;
    const __half* wto = wt + 3 * DD * DD;

    // Transpose + fp16-convert all weights (Wq pre-scaled by 1/8)
    {
        dim3 grid(DD / 32, DD / 32, 4);
        transpose_w<<<grid, dim3(32, 8)>>>(Wq, Wk, Wv, Wo, wt);
    }
    // All three projections in one launch
    {
        dim3 grid(DD / 128, 96, 1);
        proj_gemm<<<grid, 256>>>(q, kv, wtq, wtk, wtv, qh, kh, vh);
    }
    // Attention
    {
        dim3 grid(NQ / 128, HH, BB);
        attn_f16<<<grid, 256>>>(qh, kh, vh, attn);
    }
    // Row stats for fused LayerNorm
    rowstats<<<(BB * NQ) / 8, 256>>>(attn, stats);
    // Output projection with fused LN + bias
    {
        dim3 grid(DD / 128, (BB * NQ) / 128, 1);
        out_gemm<<<grid, 256>>>(attn, wto, bo, stats, gamma, beta, out);
    }
}

// round 10
// speedup vs baseline: 1.2867x; 1.0151x over previous
#include <cuda_runtime.h>
#include <cuda_fp16.h>
#include <math_constants.h>
#include <cstdint>
#include <cstddef>

#define BB 2
#define NQ 4096
#define NKV 1024
#define DD 512
#define HH 8
#define DH 64
#define LN_EPS 1e-5f

// ---------------------------------------------------------------------------
// Scratch
// ---------------------------------------------------------------------------
__device__ __half g_qh[BB * NQ * DD];    // (q @ (Wq/8)) fp16
__device__ __half g_kh[BB * NKV * DD];   // kv @ Wk fp16
__device__ __half g_vh[BB * NKV * DD];   // kv @ Wv fp16
__device__ float  g_attn[BB * NQ * DD];
__device__ float2 g_stats[BB * NQ];      // per-row (mean, rstd)
__device__ __half g_wt[4 * DD * DD];     // W^T fp16, [n][k] k-contiguous

// ---------------------------------------------------------------------------
// helpers
// ---------------------------------------------------------------------------
__device__ __forceinline__ uint32_t packh2(float lo, float hi) {
    uint32_t r;
    asm("cvt.rn.f16x2.f32 %0, %1, %2;" : "=r"(r) : "f"(hi), "f"(lo));
    return r;
}

__device__ __forceinline__ void mma_f16(float d[4], const uint32_t a[4],
                                        const uint32_t b[2]) {
    asm("mma.sync.aligned.m16n8k16.row.col.f32.f16.f16.f32 "
        "{%0,%1,%2,%3},{%4,%5,%6,%7},{%8,%9},{%0,%1,%2,%3};"
        : "+f"(d[0]), "+f"(d[1]), "+f"(d[2]), "+f"(d[3])
        : "r"(a[0]), "r"(a[1]), "r"(a[2]), "r"(a[3]), "r"(b[0]), "r"(b[1]));
}

// ---------------------------------------------------------------------------
// Weight transpose + fp16 convert: Wt[z][n][k] = fp16(W_z[k][n] * scale_z)
// ---------------------------------------------------------------------------
__global__ void __launch_bounds__(256) transpose_w(
    const float* __restrict__ Wq, const float* __restrict__ Wk,
    const float* __restrict__ Wv, const float* __restrict__ Wo,
    __half* __restrict__ Wt)
{
    __shared__ float t[32][33];
    const int z = blockIdx.z;
    const float* W = (z == 0) ? Wq : (z == 1) ? Wk : (z == 2) ? Wv : Wo;
    const float sc = (z == 0) ? 0.125f : 1.0f;
    __half* T = Wt + (size_t)z * DD * DD;
    const int tx = threadIdx.x, ty = threadIdx.y;
    const int kb = blockIdx.x * 32, nb = blockIdx.y * 32;
    #pragma unroll
    for (int j = 0; j < 4; j++)
        t[ty + j * 8][tx] = W[(size_t)(kb + ty + j * 8) * DD + nb + tx] * sc;
    __syncthreads();
    #pragma unroll
    for (int j = 0; j < 4; j++)
        T[(size_t)(nb + ty + j * 8) * DD + kb + tx] =
            __float2half_rn(t[tx][ty + j * 8]);
}

// ---------------------------------------------------------------------------
// Row stats for LN fusion: one warp per row of X[*, 512]
// ---------------------------------------------------------------------------
__global__ void __launch_bounds__(256) rowstats(
    const float* __restrict__ X, float2* __restrict__ st)
{
    const int w = threadIdx.x >> 5, lane = threadIdx.x & 31;
    const int row = blockIdx.x * 8 + w;
    const float* x = X + (size_t)row * DD;
    float s = 0.f, sq = 0.f;
    #pragma unroll
    for (int j = 0; j < 4; j++) {
        const float4 v = *(const float4*)(x + lane * 4 + j * 128);
        s += v.x + v.y + v.z + v.w;
        sq += v.x * v.x + v.y * v.y + v.z * v.z + v.w * v.w;
    }
    #pragma unroll
    for (int off = 16; off > 0; off >>= 1) {
        s += __shfl_xor_sync(0xffffffffu, s, off);
        sq += __shfl_xor_sync(0xffffffffu, sq, off);
    }
    if (lane == 0) {
        const float mean = s * (1.f / DD);
        const float var = sq * (1.f / DD) - mean * mean;
        st[row] = make_float2(mean, rsqrtf(var + LN_EPS));
    }
}

// ---------------------------------------------------------------------------
// Merged projection GEMM (fp16 out), DOUBLE-BUFFERED smem (1 barrier/K-step).
// BM=128 BN=128 BK=32, warps 4(M)x2(N). blockIdx.y: [0,64) Q, [64,80) K, [80,96) V.
// ---------------------------------------------------------------------------
__global__ void __launch_bounds__(256) proj_gemm(
    const float* __restrict__ Aq, const float* __restrict__ Akv,
    const __half* __restrict__ WtQ, const __half* __restrict__ WtK,
    const __half* __restrict__ WtV,
    __half* __restrict__ Cq, __half* __restrict__ Ck, __half* __restrict__ Cv)
{
    __shared__ uint32_t As[2][128 * 20];
    __shared__ uint32_t Bs[2][128 * 20];

    const int ty = blockIdx.y;
    const float* __restrict__ A;
    const __half* __restrict__ Wt;
    __half* __restrict__ C;
    int row0;
    if (ty < 64)      { A = Aq;  Wt = WtQ; C = Cq; row0 = ty * 128; }
    else if (ty < 80) { A = Akv; Wt = WtK; C = Ck; row0 = (ty - 64) * 128; }
    else              { A = Akv; Wt = WtV; C = Cv; row0 = (ty - 80) * 128; }

    const int tid = threadIdx.x;
    const int lane = tid & 31;
    const int g = lane >> 2, t = lane & 3;
    const int w = tid >> 5;
    const int wm = w >> 1, wn = w & 1;
    const int col0 = blockIdx.x * 128;

    const int ar = tid >> 3;
    const int af4 = tid & 7;
    const int br = tid >> 2;
    const int bf = tid & 3;

    float4 aR[4];
    uint4 bR[2];

    auto loadA = [&](int k0) {
        #pragma unroll
        for (int i = 0; i < 4; i++)
            aR[i] = *(const float4*)(A + (size_t)(row0 + ar + i * 32) * DD + k0 + af4 * 4);
    };
    auto loadB = [&](int k0) {
        #pragma unroll
        for (int i = 0; i < 2; i++)
            bR[i] = *(const uint4*)(Wt + (size_t)(col0 + br + i * 64) * DD + k0 + bf * 8);
    };

    float acc[2][8][4];
    #pragma unroll
    for (int mi = 0; mi < 2; mi++)
        #pragma unroll
        for (int ni = 0; ni < 8; ni++)
            #pragma unroll
            for (int r = 0; r < 4; r++) acc[mi][ni][r] = 0.f;

    loadA(0);
    loadB(0);

    #pragma unroll 1
    for (int s = 0; s < 16; s++) {
        const int buf = s & 1;
        #pragma unroll
        for (int i = 0; i < 4; i++)
            *(uint2*)&As[buf][(ar + i * 32) * 20 + af4 * 2] =
                make_uint2(packh2(aR[i].x, aR[i].y), packh2(aR[i].z, aR[i].w));
        #pragma unroll
        for (int i = 0; i < 2; i++)
            *(uint4*)&Bs[buf][(br + i * 64) * 20 + bf * 4] = bR[i];
        __syncthreads();

        if (s < 15) { loadA((s + 1) * 32); loadB((s + 1) * 32); }

        #pragma unroll
        for (int ks = 0; ks < 2; ks++) {
            const int ko = ks * 8;
            uint32_t af[2][4];
            #pragma unroll
            for (int mi = 0; mi < 2; mi++) {
                const int mb = wm * 32 + mi * 16;
                af[mi][0] = As[buf][(mb + g) * 20 + ko + t];
                af[mi][1] = As[buf][(mb + g + 8) * 20 + ko + t];
                af[mi][2] = As[buf][(mb + g) * 20 + ko + t + 4];
                af[mi][3] = As[buf][(mb + g + 8) * 20 + ko + t + 4];
            }
            #pragma unroll
            for (int ni = 0; ni < 8; ni++) {
                const int nb = wn * 64 + ni * 8;
                uint32_t bf2[2];
                bf2[0] = Bs[buf][(nb + g) * 20 + ko + t];
                bf2[1] = Bs[buf][(nb + g) * 20 + ko + t + 4];
                mma_f16(acc[0][ni], af[0], bf2);
                mma_f16(acc[1][ni], af[1], bf2);
            }
        }
    }

    #pragma unroll
    for (int mi = 0; mi < 2; mi++) {
        const int rr0 = row0 + wm * 32 + mi * 16 + g;
        #pragma unroll
        for (int ni = 0; ni < 8; ni++) {
            const int cc = col0 + wn * 64 + ni * 8 + 2 * t;
            *(uint32_t*)(C + (size_t)rr0 * DD + cc) =
                packh2(acc[mi][ni][0], acc[mi][ni][1]);
            *(uint32_t*)(C + (size_t)(rr0 + 8) * DD + cc) =
                packh2(acc[mi][ni][2], acc[mi][ni][3]);
        }
    }
}

// ---------------------------------------------------------------------------
// Output GEMM with fused LayerNorm, DOUBLE-BUFFERED smem.
// ---------------------------------------------------------------------------
__global__ void __launch_bounds__(256) out_gemm(
    const float* __restrict__ A, const __half* __restrict__ Wt,
    const float* __restrict__ bias, const float2* __restrict__ stats,
    const float* __restrict__ gamma, const float* __restrict__ beta,
    float* __restrict__ C)
{
    __shared__ uint32_t As[2][128 * 20];
    __shared__ uint32_t Bs[2][128 * 20];

    const int tid = threadIdx.x;
    const int lane = tid & 31;
    const int g = lane >> 2, t = lane & 3;
    const int w = tid >> 5;
    const int wm = w >> 1, wn = w & 1;
    const int row0 = blockIdx.y * 128, col0 = blockIdx.x * 128;

    const int ar = tid >> 3;
    const int af4 = tid & 7;
    const int br = tid >> 2;
    const int bf = tid & 3;

    float a_sc[4], a_sh[4];
    #pragma unroll
    for (int i = 0; i < 4; i++) {
        const float2 st = stats[row0 + ar + i * 32];
        a_sc[i] = st.y;
        a_sh[i] = -st.x * st.y;
    }

    float4 aR[4];
    uint4 bR[2];

    auto loadA = [&](int k0) {
        #pragma unroll
        for (int i = 0; i < 4; i++)
            aR[i] = *(const float4*)(A + (size_t)(row0 + ar + i * 32) * DD + k0 + af4 * 4);
    };
    auto loadB = [&](int k0) {
        #pragma unroll
        for (int i = 0; i < 2; i++)
            bR[i] = *(const uint4*)(Wt + (size_t)(col0 + br + i * 64) * DD + k0 + bf * 8);
    };

    float acc[2][8][4];
    #pragma unroll
    for (int mi = 0; mi < 2; mi++)
        #pragma unroll
        for (int ni = 0; ni < 8; ni++)
            #pragma unroll
            for (int r = 0; r < 4; r++) acc[mi][ni][r] = 0.f;

    loadA(0);
    loadB(0);

    #pragma unroll 1
    for (int s = 0; s < 16; s++) {
        const int buf = s & 1;
        const int k0 = s * 32;
        const float4 g4 = *(const float4*)(gamma + k0 + af4 * 4);
        const float4 b4 = *(const float4*)(beta + k0 + af4 * 4);
        #pragma unroll
        for (int i = 0; i < 4; i++) {
            float4 v = aR[i];
            v.x = fmaf(fmaf(v.x, a_sc[i], a_sh[i]), g4.x, b4.x);
            v.y = fmaf(fmaf(v.y, a_sc[i], a_sh[i]), g4.y, b4.y);
            v.z = fmaf(fmaf(v.z, a_sc[i], a_sh[i]), g4.z, b4.z);
            v.w = fmaf(fmaf(v.w, a_sc[i], a_sh[i]), g4.w, b4.w);
            *(uint2*)&As[buf][(ar + i * 32) * 20 + af4 * 2] =
                make_uint2(packh2(v.x, v.y), packh2(v.z, v.w));
        }
        #pragma unroll
        for (int i = 0; i < 2; i++)
            *(uint4*)&Bs[buf][(br + i * 64) * 20 + bf * 4] = bR[i];
        __syncthreads();

        if (s < 15) { loadA(k0 + 32); loadB(k0 + 32); }

        #pragma unroll
        for (int ks = 0; ks < 2; ks++) {
            const int ko = ks * 8;
            uint32_t af[2][4];
            #pragma unroll
            for (int mi = 0; mi < 2; mi++) {
                const int mb = wm * 32 + mi * 16;
                af[mi][0] = As[buf][(mb + g) * 20 + ko + t];
                af[mi][1] = As[buf][(mb + g + 8) * 20 + ko + t];
                af[mi][2] = As[buf][(mb + g) * 20 + ko + t + 4];
                af[mi][3] = As[buf][(mb + g + 8) * 20 + ko + t + 4];
            }
            #pragma unroll
            for (int ni = 0; ni < 8; ni++) {
                const int nb = wn * 64 + ni * 8;
                uint32_t bf2[2];
                bf2[0] = Bs[buf][(nb + g) * 20 + ko + t];
                bf2[1] = Bs[buf][(nb + g) * 20 + ko + t + 4];
                mma_f16(acc[0][ni], af[0], bf2);
                mma_f16(acc[1][ni], af[1], bf2);
            }
        }
    }

    #pragma unroll
    for (int mi = 0; mi < 2; mi++) {
        const int rr0 = row0 + wm * 32 + mi * 16 + g;
        #pragma unroll
        for (int ni = 0; ni < 8; ni++) {
            const int cc = col0 + wn * 64 + ni * 8 + 2 * t;
            const float2 bv = *(const float2*)(bias + cc);
            *(float2*)(C + (size_t)rr0 * DD + cc) =
                make_float2(acc[mi][ni][0] + bv.x, acc[mi][ni][1] + bv.y);
            *(float2*)(C + (size_t)(rr0 + 8) * DD + cc) =
                make_float2(acc[mi][ni][2] + bv.x, acc[mi][ni][3] + bv.y);
        }
    }
}

// ---------------------------------------------------------------------------
// Flash attention: register prefetch + DOUBLE-BUFFERED K/V smem
// (one barrier per chunk). Dynamic smem: Qs + 2xKs + 2xVs = 54,272 B.
// ---------------------------------------------------------------------------
#define ATTN_SMEM_BYTES ((128 * 36 + 2 * 64 * 36 + 2 * 32 * 68) * 4)

__global__ void __launch_bounds__(256) attn_f16(
    const __half* __restrict__ Qh, const __half* __restrict__ Kh,
    const __half* __restrict__ Vh, float* __restrict__ O)
{
    extern __shared__ uint32_t smd[];
    uint32_t* Qs  = smd;                       // 128*36
    uint32_t* KsB = Qs + 128 * 36;             // 2 x 64*36
    uint32_t* VsB = KsB + 2 * 64 * 36;         // 2 x 32*68

    const int tile = (NQ / 128 - 1) - blockIdx.x;   // big tiles first
    const int h = blockIdx.y, b = blockIdx.z;
    const int tid = threadIdx.x;
    const int lane = tid & 31;
    const int g = lane >> 2, t = lane & 3;
    const int w = tid >> 5;

    const size_t qbase = ((size_t)b * NQ + (size_t)tile * 128) * DD + (size_t)h * DH;
    const size_t kvbase = (size_t)b * NKV * DD + (size_t)h * DH;

    // Q tile: direct fp16 copy
    #pragma unroll
    for (int i = 0; i < 4; i++) {
        const int idx = tid + i * 256;
        const int r = idx >> 3, c = idx & 7;
        const uint4 u = *(const uint4*)(Qh + qbase + (size_t)r * DD + c * 8);
        *(uint4*)&Qs[r * 36 + c * 4] = u;
    }

    float oacc[8][4];
    #pragma unroll
    for (int ni = 0; ni < 8; ni++)
        #pragma unroll
        for (int r = 0; r < 4; r++) oacc[ni][r] = 0.f;
    float m0 = -CUDART_INF_F, m1 = -CUDART_INF_F, l0 = 0.f, l1 = 0.f;

    const int row0 = tile * 128 + w * 16 + g;
    const int lim0 = row0 >> 2;
    const int lim1 = (row0 + 8) >> 2;
    const int nch = (32 * tile + 95) >> 6;

    const int kr8 = tid >> 3, kc8 = tid & 7;
    const int vjp = tid >> 4, vd4 = tid & 15;
    uint4 kR[2];
    uint2 vaR[2], vbR[2];

    auto loadKV = [&](int k0) {
        #pragma unroll
        for (int i = 0; i < 2; i++)
            kR[i] = *(const uint4*)(Kh + kvbase + (size_t)(k0 + kr8 + i * 32) * DD + kc8 * 8);
        #pragma unroll
        for (int i = 0; i < 2; i++) {
            const int jp = vjp + i * 16;
            vaR[i] = *(const uint2*)(Vh + kvbase + (size_t)(k0 + 2 * jp) * DD + vd4 * 4);
            vbR[i] = *(const uint2*)(Vh + kvbase + (size_t)(k0 + 2 * jp + 1) * DD + vd4 * 4);
        }
    };

    loadKV(0);

    #pragma unroll 1
    for (int c = 0; c < nch; c++) {
        const int k0 = c * 64;
        uint32_t* Ks = KsB + (c & 1) * (64 * 36);
        uint32_t* Vs = VsB + (c & 1) * (32 * 68);

        // store this chunk (buffer free: its last readers finished before the
        // barrier in iteration c-1)
        #pragma unroll
        for (int i = 0; i < 2; i++)
            *(uint4*)&Ks[(kr8 + i * 32) * 36 + kc8 * 4] = kR[i];
        #pragma unroll
        for (int i = 0; i < 2; i++) {
            uint4 u;
            u.x = __byte_perm(vaR[i].x, vbR[i].x, 0x5410);
            u.y = __byte_perm(vaR[i].x, vbR[i].x, 0x7632);
            u.z = __byte_perm(vaR[i].y, vbR[i].y, 0x5410);
            u.w = __byte_perm(vaR[i].y, vbR[i].y, 0x7632);
            *(uint4*)&Vs[(vjp + i * 16) * 68 + vd4 * 4] = u;
        }
        __syncthreads();
        if (c + 1 < nch) loadKV(k0 + 64);   // overlap with compute below

        // S = Q @ K^T
        float pf[8][4];
        #pragma unroll
        for (int ni = 0; ni < 8; ni++)
            #pragma unroll
            for (int r = 0; r < 4; r++) pf[ni][r] = 0.f;

        const int mb = w * 16;
        #pragma unroll
        for (int kt = 0; kt < 4; kt++) {
            const int ko = kt * 8;
            uint32_t af[4];
            af[0] = Qs[(mb + g) * 36 + ko + t];
            af[1] = Qs[(mb + g + 8) * 36 + ko + t];
            af[2] = Qs[(mb + g) * 36 + ko + t + 4];
            af[3] = Qs[(mb + g + 8) * 36 + ko + t + 4];
            #pragma unroll
            for (int ni = 0; ni < 8; ni++) {
                uint32_t bf2[2];
                bf2[0] = Ks[(ni * 8 + g) * 36 + ko + t];
                bf2[1] = Ks[(ni * 8 + g) * 36 + ko + t + 4];
                mma_f16(pf[ni], af, bf2);
            }
        }

        // mask (diagonal chunk only) + online softmax
        if (c == nch - 1) {
            #pragma unroll
            for (int ni = 0; ni < 8; ni++) {
                const int j = k0 + ni * 8 + 2 * t;
                if (j > lim0)     pf[ni][0] = -CUDART_INF_F;
                if (j + 1 > lim0) pf[ni][1] = -CUDART_INF_F;
                if (j > lim1)     pf[ni][2] = -CUDART_INF_F;
                if (j + 1 > lim1) pf[ni][3] = -CUDART_INF_F;
            }
        }

        float mx0 = -CUDART_INF_F, mx1 = -CUDART_INF_F;
        #pragma unroll
        for (int ni = 0; ni < 8; ni++) {
            mx0 = fmaxf(mx0, fmaxf(pf[ni][0], pf[ni][1]));
            mx1 = fmaxf(mx1, fmaxf(pf[ni][2], pf[ni][3]));
        }
        mx0 = fmaxf(mx0, __shfl_xor_sync(0xffffffffu, mx0, 1));
        mx0 = fmaxf(mx0, __shfl_xor_sync(0xffffffffu, mx0, 2));
        mx1 = fmaxf(mx1, __shfl_xor_sync(0xffffffffu, mx1, 1));
        mx1 = fmaxf(mx1, __shfl_xor_sync(0xffffffffu, mx1, 2));

        const float mn0 = fmaxf(m0, mx0), mn1 = fmaxf(m1, mx1);
        const float al0 = __expf(m0 - mn0), al1 = __expf(m1 - mn1);
        m0 = mn0; m1 = mn1;

        float rs0 = 0.f, rs1 = 0.f;
        #pragma unroll
        for (int ni = 0; ni < 8; ni++) {
            pf[ni][0] = __expf(pf[ni][0] - mn0);
            pf[ni][1] = __expf(pf[ni][1] - mn0);
            pf[ni][2] = __expf(pf[ni][2] - mn1);
            pf[ni][3] = __expf(pf[ni][3] - mn1);
            rs0 += pf[ni][0] + pf[ni][1];
            rs1 += pf[ni][2] + pf[ni][3];
        }
        rs0 += __shfl_xor_sync(0xffffffffu, rs0, 1);
        rs0 += __shfl_xor_sync(0xffffffffu, rs0, 2);
        rs1 += __shfl_xor_sync(0xffffffffu, rs1, 1);
        rs1 += __shfl_xor_sync(0xffffffffu, rs1, 2);
        l0 = l0 * al0 + rs0;
        l1 = l1 * al1 + rs1;

        #pragma unroll
        for (int ni = 0; ni < 8; ni++) {
            oacc[ni][0] *= al0; oacc[ni][1] *= al0;
            oacc[ni][2] *= al1; oacc[ni][3] *= al1;
        }

        // O += P @ V
        #pragma unroll
        for (int kt = 0; kt < 4; kt++) {
            uint32_t a[4];
            a[0] = packh2(pf[2 * kt][0],     pf[2 * kt][1]);
            a[1] = packh2(pf[2 * kt][2],     pf[2 * kt][3]);
            a[2] = packh2(pf[2 * kt + 1][0], pf[2 * kt + 1][1]);
            a[3] = packh2(pf[2 * kt + 1][2], pf[2 * kt + 1][3]);
            const int jp0 = 8 * kt + t;
            #pragma unroll
            for (int ni = 0; ni < 8; ni++) {
                uint32_t bf2[2];
                bf2[0] = Vs[jp0 * 68 + ni * 8 + g];
                bf2[1] = Vs[(jp0 + 4) * 68 + ni * 8 + g];
                mma_f16(oacc[ni], a, bf2);
            }
        }
    }

    const float inv0 = 1.f / l0, inv1 = 1.f / l1;
    const int lr0 = w * 16 + g;
    #pragma unroll
    for (int ni = 0; ni < 8; ni++) {
        const int cc = ni * 8 + 2 * t;
        *(float2*)(O + qbase + (size_t)lr0 * DD + cc) =
            make_float2(oacc[ni][0] * inv0, oacc[ni][1] * inv0);
        *(float2*)(O + qbase + (size_t)(lr0 + 8) * DD + cc) =
            make_float2(oacc[ni][2] * inv1, oacc[ni][3] * inv1);
    }
}

// ---------------------------------------------------------------------------
// Launch
// ---------------------------------------------------------------------------
extern "C" void kernel_launch(void* const* d_in, const int* in_sizes, int n_in,
                              void* d_out, int out_size)
{
    (void)in_sizes; (void)n_in; (void)out_size;

    const float* q     = (const float*)d_in[0];
    const float* kv    = (const float*)d_in[1];
    const float* Wq    = (const float*)d_in[2];
    const float* Wk    = (const float*)d_in[3];
    const float* Wv    = (const float*)d_in[4];
    const float* Wo    = (const float*)d_in[5];
    const float* bo    = (const float*)d_in[6];
    const float* gamma = (const float*)d_in[7];
    const float* beta  = (const float*)d_in[8];
    float* out = (float*)d_out;

    __half *qh, *kh, *vh, *wt;
    float *attn;
    float2 *stats;
    cudaGetSymbolAddress((void**)&qh,    g_qh);
    cudaGetSymbolAddress((void**)&kh,    g_kh);
    cudaGetSymbolAddress((void**)&vh,    g_vh);
    cudaGetSymbolAddress((void**)&attn,  g_attn);
    cudaGetSymbolAddress((void**)&stats, g_stats);
    cudaGetSymbolAddress((void**)&wt,    g_wt);

    cudaFuncSetAttribute(attn_f16,
                         cudaFuncAttributeMaxDynamicSharedMemorySize,
                         ATTN_SMEM_BYTES);

    const __half* wtq = wt;
    const __half* wtk = wt + 1 * DD * DD;
    const __half* wtv = wt + 2 * DD * DD;
    const __half* wto = wt + 3 * DD * DD;

    // Transpose + fp16-convert all weights (Wq pre-scaled by 1/8)
    {
        dim3 grid(DD / 32, DD / 32, 4);
        transpose_w<<<grid, dim3(32, 8)>>>(Wq, Wk, Wv, Wo, wt);
    }
    // All three projections in one launch
    {
        dim3 grid(DD / 128, 96, 1);
        proj_gemm<<<grid, 256>>>(q, kv, wtq, wtk, wtv, qh, kh, vh);
    }
    // Attention
    {
        dim3 grid(NQ / 128, HH, BB);
        attn_f16<<<grid, 256, ATTN_SMEM_BYTES>>>(qh, kh, vh, attn);
    }
    // Row stats for fused LayerNorm
    rowstats<<<(BB * NQ) / 8, 256>>>(attn, stats);
    // Output projection with fused LN + bias
    {
        dim3 grid(DD / 128, (BB * NQ) / 128, 1);
        out_gemm<<<grid, 256>>>(attn, wto, bo, stats, gamma, beta, out);
    }
}

// round 11
// speedup vs baseline: 1.3722x; 1.0664x over previous
#include <cuda_runtime.h>
#include <cuda_fp16.h>
#include <math_constants.h>
#include <cstdint>
#include <cstddef>

#define BB 2
#define NQ 4096
#define NKV 1024
#define DD 512
#define HH 8
#define DH 64
#define LN_EPS 1e-5f

// ---------------------------------------------------------------------------
// Scratch
// ---------------------------------------------------------------------------
__device__ __half g_qh[BB * NQ * DD];    // (q @ (Wq/8)) fp16
__device__ __half g_kh[BB * NKV * DD];   // kv @ Wk fp16
__device__ __half g_vh[BB * NKV * DD];   // kv @ Wv fp16
__device__ __half g_attn[BB * NQ * DD];  // attention output, fp16
__device__ float2 g_psum[BB * NQ * HH];  // per-(row, head) partial (sum, sumsq)
__device__ __half g_wt[4 * DD * DD];     // W^T fp16, [n][k] k-contiguous

// ---------------------------------------------------------------------------
// helpers
// ---------------------------------------------------------------------------
__device__ __forceinline__ uint32_t packh2(float lo, float hi) {
    uint32_t r;
    asm("cvt.rn.f16x2.f32 %0, %1, %2;" : "=r"(r) : "f"(hi), "f"(lo));
    return r;
}

__device__ __forceinline__ void mma_f16(float d[4], const uint32_t a[4],
                                        const uint32_t b[2]) {
    asm("mma.sync.aligned.m16n8k16.row.col.f32.f16.f16.f32 "
        "{%0,%1,%2,%3},{%4,%5,%6,%7},{%8,%9},{%0,%1,%2,%3};"
        : "+f"(d[0]), "+f"(d[1]), "+f"(d[2]), "+f"(d[3])
        : "r"(a[0]), "r"(a[1]), "r"(a[2]), "r"(a[3]), "r"(b[0]), "r"(b[1]));
}

// ---------------------------------------------------------------------------
// Weight transpose + fp16 convert: Wt[z][n][k] = fp16(W_z[k][n] * scale_z)
// ---------------------------------------------------------------------------
__global__ void __launch_bounds__(256) transpose_w(
    const float* __restrict__ Wq, const float* __restrict__ Wk,
    const float* __restrict__ Wv, const float* __restrict__ Wo,
    __half* __restrict__ Wt)
{
    __shared__ float t[32][33];
    const int z = blockIdx.z;
    const float* W = (z == 0) ? Wq : (z == 1) ? Wk : (z == 2) ? Wv : Wo;
    const float sc = (z == 0) ? 0.125f : 1.0f;
    __half* T = Wt + (size_t)z * DD * DD;
    const int tx = threadIdx.x, ty = threadIdx.y;
    const int kb = blockIdx.x * 32, nb = blockIdx.y * 32;
    #pragma unroll
    for (int j = 0; j < 4; j++)
        t[ty + j * 8][tx] = W[(size_t)(kb + ty + j * 8) * DD + nb + tx] * sc;
    __syncthreads();
    #pragma unroll
    for (int j = 0; j < 4; j++)
        T[(size_t)(nb + ty + j * 8) * DD + kb + tx] =
            __float2half_rn(t[tx][ty + j * 8]);
}

// ---------------------------------------------------------------------------
// Merged projection GEMM (fp16 out), double-buffered smem.
// BM=128 BN=128 BK=32, warps 4(M)x2(N). blockIdx.y: [0,64) Q, [64,80) K, [80,96) V.
// ---------------------------------------------------------------------------
__global__ void __launch_bounds__(256) proj_gemm(
    const float* __restrict__ Aq, const float* __restrict__ Akv,
    const __half* __restrict__ WtQ, const __half* __restrict__ WtK,
    const __half* __restrict__ WtV,
    __half* __restrict__ Cq, __half* __restrict__ Ck, __half* __restrict__ Cv)
{
    __shared__ uint32_t As[2][128 * 20];
    __shared__ uint32_t Bs[2][128 * 20];

    const int ty = blockIdx.y;
    const float* __restrict__ A;
    const __half* __restrict__ Wt;
    __half* __restrict__ C;
    int row0;
    if (ty < 64)      { A = Aq;  Wt = WtQ; C = Cq; row0 = ty * 128; }
    else if (ty < 80) { A = Akv; Wt = WtK; C = Ck; row0 = (ty - 64) * 128; }
    else              { A = Akv; Wt = WtV; C = Cv; row0 = (ty - 80) * 128; }

    const int tid = threadIdx.x;
    const int lane = tid & 31;
    const int g = lane >> 2, t = lane & 3;
    const int w = tid >> 5;
    const int wm = w >> 1, wn = w & 1;
    const int col0 = blockIdx.x * 128;

    const int ar = tid >> 3;
    const int af4 = tid & 7;
    const int br = tid >> 2;
    const int bf = tid & 3;

    float4 aR[4];
    uint4 bR[2];

    auto loadA = [&](int k0) {
        #pragma unroll
        for (int i = 0; i < 4; i++)
            aR[i] = *(const float4*)(A + (size_t)(row0 + ar + i * 32) * DD + k0 + af4 * 4);
    };
    auto loadB = [&](int k0) {
        #pragma unroll
        for (int i = 0; i < 2; i++)
            bR[i] = *(const uint4*)(Wt + (size_t)(col0 + br + i * 64) * DD + k0 + bf * 8);
    };

    float acc[2][8][4];
    #pragma unroll
    for (int mi = 0; mi < 2; mi++)
        #pragma unroll
        for (int ni = 0; ni < 8; ni++)
            #pragma unroll
            for (int r = 0; r < 4; r++) acc[mi][ni][r] = 0.f;

    loadA(0);
    loadB(0);

    #pragma unroll 1
    for (int s = 0; s < 16; s++) {
        const int buf = s & 1;
        #pragma unroll
        for (int i = 0; i < 4; i++)
            *(uint2*)&As[buf][(ar + i * 32) * 20 + af4 * 2] =
                make_uint2(packh2(aR[i].x, aR[i].y), packh2(aR[i].z, aR[i].w));
        #pragma unroll
        for (int i = 0; i < 2; i++)
            *(uint4*)&Bs[buf][(br + i * 64) * 20 + bf * 4] = bR[i];
        __syncthreads();

        if (s < 15) { loadA((s + 1) * 32); loadB((s + 1) * 32); }

        #pragma unroll
        for (int ks = 0; ks < 2; ks++) {
            const int ko = ks * 8;
            uint32_t af[2][4];
            #pragma unroll
            for (int mi = 0; mi < 2; mi++) {
                const int mb = wm * 32 + mi * 16;
                af[mi][0] = As[buf][(mb + g) * 20 + ko + t];
                af[mi][1] = As[buf][(mb + g + 8) * 20 + ko + t];
                af[mi][2] = As[buf][(mb + g) * 20 + ko + t + 4];
                af[mi][3] = As[buf][(mb + g + 8) * 20 + ko + t + 4];
            }
            #pragma unroll
            for (int ni = 0; ni < 8; ni++) {
                const int nb = wn * 64 + ni * 8;
                uint32_t bf2[2];
                bf2[0] = Bs[buf][(nb + g) * 20 + ko + t];
                bf2[1] = Bs[buf][(nb + g) * 20 + ko + t + 4];
                mma_f16(acc[0][ni], af[0], bf2);
                mma_f16(acc[1][ni], af[1], bf2);
            }
        }
    }

    #pragma unroll
    for (int mi = 0; mi < 2; mi++) {
        const int rr0 = row0 + wm * 32 + mi * 16 + g;
        #pragma unroll
        for (int ni = 0; ni < 8; ni++) {
            const int cc = col0 + wn * 64 + ni * 8 + 2 * t;
            *(uint32_t*)(C + (size_t)rr0 * DD + cc) =
                packh2(acc[mi][ni][0], acc[mi][ni][1]);
            *(uint32_t*)(C + (size_t)(rr0 + 8) * DD + cc) =
                packh2(acc[mi][ni][2], acc[mi][ni][3]);
        }
    }
}

// ---------------------------------------------------------------------------
// Output GEMM with fused LayerNorm: C = LN(A)@Wo + bias. A is fp16; LN stats
// assembled from per-head partial sums (g_psum) in the prologue.
// Double-buffered smem.
// ---------------------------------------------------------------------------
__global__ void __launch_bounds__(256) out_gemm(
    const __half* __restrict__ A, const __half* __restrict__ Wt,
    const float* __restrict__ bias, const float2* __restrict__ psum,
    const float* __restrict__ gamma, const float* __restrict__ beta,
    float* __restrict__ C)
{
    __shared__ uint32_t As[2][128 * 20];
    __shared__ uint32_t Bs[2][128 * 20];

    const int tid = threadIdx.x;
    const int lane = tid & 31;
    const int g = lane >> 2, t = lane & 3;
    const int w = tid >> 5;
    const int wm = w >> 1, wn = w & 1;
    const int row0 = blockIdx.y * 128, col0 = blockIdx.x * 128;

    const int ar = tid >> 3;
    const int af4 = tid & 7;
    const int br = tid >> 2;
    const int bf = tid & 3;

    // assemble LN stats for this thread's 4 A-rows from 8 head-partials each
    float a_sc[4], a_sh[4];
    #pragma unroll
    for (int i = 0; i < 4; i++) {
        const int gr = row0 + ar + i * 32;
        float S = 0.f, Q = 0.f;
        #pragma unroll
        for (int hh = 0; hh < HH; hh++) {
            const float2 ps = psum[gr * HH + hh];
            S += ps.x; Q += ps.y;
        }
        const float mean = S * (1.f / DD);
        const float var = Q * (1.f / DD) - mean * mean;
        const float rs = rsqrtf(var + LN_EPS);
        a_sc[i] = rs;
        a_sh[i] = -mean * rs;
    }

    uint2 aR[4];
    uint4 bR[2];

    auto loadA = [&](int k0) {
        #pragma unroll
        for (int i = 0; i < 4; i++)
            aR[i] = *(const uint2*)(A + (size_t)(row0 + ar + i * 32) * DD + k0 + af4 * 4);
    };
    auto loadB = [&](int k0) {
        #pragma unroll
        for (int i = 0; i < 2; i++)
            bR[i] = *(const uint4*)(Wt + (size_t)(col0 + br + i * 64) * DD + k0 + bf * 8);
    };

    float acc[2][8][4];
    #pragma unroll
    for (int mi = 0; mi < 2; mi++)
        #pragma unroll
        for (int ni = 0; ni < 8; ni++)
            #pragma unroll
            for (int r = 0; r < 4; r++) acc[mi][ni][r] = 0.f;

    loadA(0);
    loadB(0);

    #pragma unroll 1
    for (int s = 0; s < 16; s++) {
        const int buf = s & 1;
        const int k0 = s * 32;
        const float4 g4 = *(const float4*)(gamma + k0 + af4 * 4);
        const float4 b4 = *(const float4*)(beta + k0 + af4 * 4);
        #pragma unroll
        for (int i = 0; i < 4; i++) {
            const float2 f01 = __half22float2(*(__half2*)&aR[i].x);
            const float2 f23 = __half22float2(*(__half2*)&aR[i].y);
            float4 v;
            v.x = fmaf(fmaf(f01.x, a_sc[i], a_sh[i]), g4.x, b4.x);
            v.y = fmaf(fmaf(f01.y, a_sc[i], a_sh[i]), g4.y, b4.y);
            v.z = fmaf(fmaf(f23.x, a_sc[i], a_sh[i]), g4.z, b4.z);
            v.w = fmaf(fmaf(f23.y, a_sc[i], a_sh[i]), g4.w, b4.w);
            *(uint2*)&As[buf][(ar + i * 32) * 20 + af4 * 2] =
                make_uint2(packh2(v.x, v.y), packh2(v.z, v.w));
        }
        #pragma unroll
        for (int i = 0; i < 2; i++)
            *(uint4*)&Bs[buf][(br + i * 64) * 20 + bf * 4] = bR[i];
        __syncthreads();

        if (s < 15) { loadA(k0 + 32); loadB(k0 + 32); }

        #pragma unroll
        for (int ks = 0; ks < 2; ks++) {
            const int ko = ks * 8;
            uint32_t af[2][4];
            #pragma unroll
            for (int mi = 0; mi < 2; mi++) {
                const int mb = wm * 32 + mi * 16;
                af[mi][0] = As[buf][(mb + g) * 20 + ko + t];
                af[mi][1] = As[buf][(mb + g + 8) * 20 + ko + t];
                af[mi][2] = As[buf][(mb + g) * 20 + ko + t + 4];
                af[mi][3] = As[buf][(mb + g + 8) * 20 + ko + t + 4];
            }
            #pragma unroll
            for (int ni = 0; ni < 8; ni++) {
                const int nb = wn * 64 + ni * 8;
                uint32_t bf2[2];
                bf2[0] = Bs[buf][(nb + g) * 20 + ko + t];
                bf2[1] = Bs[buf][(nb + g) * 20 + ko + t + 4];
                mma_f16(acc[0][ni], af[0], bf2);
                mma_f16(acc[1][ni], af[1], bf2);
            }
        }
    }

    #pragma unroll
    for (int mi = 0; mi < 2; mi++) {
        const int rr0 = row0 + wm * 32 + mi * 16 + g;
        #pragma unroll
        for (int ni = 0; ni < 8; ni++) {
            const int cc = col0 + wn * 64 + ni * 8 + 2 * t;
            const float2 bv = *(const float2*)(bias + cc);
            *(float2*)(C + (size_t)rr0 * DD + cc) =
                make_float2(acc[mi][ni][0] + bv.x, acc[mi][ni][1] + bv.y);
            *(float2*)(C + (size_t)(rr0 + 8) * DD + cc) =
                make_float2(acc[mi][ni][2] + bv.x, acc[mi][ni][3] + bv.y);
        }
    }
}

// ---------------------------------------------------------------------------
// Flash attention: register prefetch + double-buffered K/V smem. fp16 output,
// per-(row, head) LN partial sums computed in the epilogue (fp32, pre-round).
// ---------------------------------------------------------------------------
#define ATTN_SMEM_BYTES ((128 * 36 + 2 * 64 * 36 + 2 * 32 * 68) * 4)

__global__ void __launch_bounds__(256) attn_f16(
    const __half* __restrict__ Qh, const __half* __restrict__ Kh,
    const __half* __restrict__ Vh, __half* __restrict__ O,
    float2* __restrict__ psum)
{
    extern __shared__ uint32_t smd[];
    uint32_t* Qs  = smd;                       // 128*36
    uint32_t* KsB = Qs + 128 * 36;             // 2 x 64*36
    uint32_t* VsB = KsB + 2 * 64 * 36;         // 2 x 32*68

    const int tile = (NQ / 128 - 1) - blockIdx.x;   // big tiles first
    const int h = blockIdx.y, b = blockIdx.z;
    const int tid = threadIdx.x;
    const int lane = tid & 31;
    const int g = lane >> 2, t = lane & 3;
    const int w = tid >> 5;

    const size_t qbase = ((size_t)b * NQ + (size_t)tile * 128) * DD + (size_t)h * DH;
    const size_t kvbase = (size_t)b * NKV * DD + (size_t)h * DH;

    // Q tile: direct fp16 copy
    #pragma unroll
    for (int i = 0; i < 4; i++) {
        const int idx = tid + i * 256;
        const int r = idx >> 3, c = idx & 7;
        const uint4 u = *(const uint4*)(Qh + qbase + (size_t)r * DD + c * 8);
        *(uint4*)&Qs[r * 36 + c * 4] = u;
    }

    float oacc[8][4];
    #pragma unroll
    for (int ni = 0; ni < 8; ni++)
        #pragma unroll
        for (int r = 0; r < 4; r++) oacc[ni][r] = 0.f;
    float m0 = -CUDART_INF_F, m1 = -CUDART_INF_F, l0 = 0.f, l1 = 0.f;

    const int row0 = tile * 128 + w * 16 + g;
    const int lim0 = row0 >> 2;
    const int lim1 = (row0 + 8) >> 2;
    const int nch = (32 * tile + 95) >> 6;

    const int kr8 = tid >> 3, kc8 = tid & 7;
    const int vjp = tid >> 4, vd4 = tid & 15;
    uint4 kR[2];
    uint2 vaR[2], vbR[2];

    auto loadKV = [&](int k0) {
        #pragma unroll
        for (int i = 0; i < 2; i++)
            kR[i] = *(const uint4*)(Kh + kvbase + (size_t)(k0 + kr8 + i * 32) * DD + kc8 * 8);
        #pragma unroll
        for (int i = 0; i < 2; i++) {
            const int jp = vjp + i * 16;
            vaR[i] = *(const uint2*)(Vh + kvbase + (size_t)(k0 + 2 * jp) * DD + vd4 * 4);
            vbR[i] = *(const uint2*)(Vh + kvbase + (size_t)(k0 + 2 * jp + 1) * DD + vd4 * 4);
        }
    };

    loadKV(0);

    #pragma unroll 1
    for (int c = 0; c < nch; c++) {
        const int k0 = c * 64;
        uint32_t* Ks = KsB + (c & 1) * (64 * 36);
        uint32_t* Vs = VsB + (c & 1) * (32 * 68);

        #pragma unroll
        for (int i = 0; i < 2; i++)
            *(uint4*)&Ks[(kr8 + i * 32) * 36 + kc8 * 4] = kR[i];
        #pragma unroll
        for (int i = 0; i < 2; i++) {
            uint4 u;
            u.x = __byte_perm(vaR[i].x, vbR[i].x, 0x5410);
            u.y = __byte_perm(vaR[i].x, vbR[i].x, 0x7632);
            u.z = __byte_perm(vaR[i].y, vbR[i].y, 0x5410);
            u.w = __byte_perm(vaR[i].y, vbR[i].y, 0x7632);
            *(uint4*)&Vs[(vjp + i * 16) * 68 + vd4 * 4] = u;
        }
        __syncthreads();
        if (c + 1 < nch) loadKV(k0 + 64);   // overlap with compute below

        // S = Q @ K^T
        float pf[8][4];
        #pragma unroll
        for (int ni = 0; ni < 8; ni++)
            #pragma unroll
            for (int r = 0; r < 4; r++) pf[ni][r] = 0.f;

        const int mb = w * 16;
        #pragma unroll
        for (int kt = 0; kt < 4; kt++) {
            const int ko = kt * 8;
            uint32_t af[4];
            af[0] = Qs[(mb + g) * 36 + ko + t];
            af[1] = Qs[(mb + g + 8) * 36 + ko + t];
            af[2] = Qs[(mb + g) * 36 + ko + t + 4];
            af[3] = Qs[(mb + g + 8) * 36 + ko + t + 4];
            #pragma unroll
            for (int ni = 0; ni < 8; ni++) {
                uint32_t bf2[2];
                bf2[0] = Ks[(ni * 8 + g) * 36 + ko + t];
                bf2[1] = Ks[(ni * 8 + g) * 36 + ko + t + 4];
                mma_f16(pf[ni], af, bf2);
            }
        }

        // mask (diagonal chunk only) + online softmax
        if (c == nch - 1) {
            #pragma unroll
            for (int ni = 0; ni < 8; ni++) {
                const int j = k0 + ni * 8 + 2 * t;
                if (j > lim0)     pf[ni][0] = -CUDART_INF_F;
                if (j + 1 > lim0) pf[ni][1] = -CUDART_INF_F;
                if (j > lim1)     pf[ni][2] = -CUDART_INF_F;
                if (j + 1 > lim1) pf[ni][3] = -CUDART_INF_F;
            }
        }

        float mx0 = -CUDART_INF_F, mx1 = -CUDART_INF_F;
        #pragma unroll
        for (int ni = 0; ni < 8; ni++) {
            mx0 = fmaxf(mx0, fmaxf(pf[ni][0], pf[ni][1]));
            mx1 = fmaxf(mx1, fmaxf(pf[ni][2], pf[ni][3]));
        }
        mx0 = fmaxf(mx0, __shfl_xor_sync(0xffffffffu, mx0, 1));
        mx0 = fmaxf(mx0, __shfl_xor_sync(0xffffffffu, mx0, 2));
        mx1 = fmaxf(mx1, __shfl_xor_sync(0xffffffffu, mx1, 1));
        mx1 = fmaxf(mx1, __shfl_xor_sync(0xffffffffu, mx1, 2));

        const float mn0 = fmaxf(m0, mx0), mn1 = fmaxf(m1, mx1);
        const float al0 = __expf(m0 - mn0), al1 = __expf(m1 - mn1);
        m0 = mn0; m1 = mn1;

        float rs0 = 0.f, rs1 = 0.f;
        #pragma unroll
        for (int ni = 0; ni < 8; ni++) {
            pf[ni][0] = __expf(pf[ni][0] - mn0);
            pf[ni][1] = __expf(pf[ni][1] - mn0);
            pf[ni][2] = __expf(pf[ni][2] - mn1);
            pf[ni][3] = __expf(pf[ni][3] - mn1);
            rs0 += pf[ni][0] + pf[ni][1];
            rs1 += pf[ni][2] + pf[ni][3];
        }
        rs0 += __shfl_xor_sync(0xffffffffu, rs0, 1);
        rs0 += __shfl_xor_sync(0xffffffffu, rs0, 2);
        rs1 += __shfl_xor_sync(0xffffffffu, rs1, 1);
        rs1 += __shfl_xor_sync(0xffffffffu, rs1, 2);
        l0 = l0 * al0 + rs0;
        l1 = l1 * al1 + rs1;

        #pragma unroll
        for (int ni = 0; ni < 8; ni++) {
            oacc[ni][0] *= al0; oacc[ni][1] *= al0;
            oacc[ni][2] *= al1; oacc[ni][3] *= al1;
        }

        // O += P @ V
        #pragma unroll
        for (int kt = 0; kt < 4; kt++) {
            uint32_t a[4];
            a[0] = packh2(pf[2 * kt][0],     pf[2 * kt][1]);
            a[1] = packh2(pf[2 * kt][2],     pf[2 * kt][3]);
            a[2] = packh2(pf[2 * kt + 1][0], pf[2 * kt + 1][1]);
            a[3] = packh2(pf[2 * kt + 1][2], pf[2 * kt + 1][3]);
            const int jp0 = 8 * kt + t;
            #pragma unroll
            for (int ni = 0; ni < 8; ni++) {
                uint32_t bf2[2];
                bf2[0] = Vs[jp0 * 68 + ni * 8 + g];
                bf2[1] = Vs[(jp0 + 4) * 68 + ni * 8 + g];
                mma_f16(oacc[ni], a, bf2);
            }
        }
    }

    // Epilogue: normalize, fp16 store, and per-(row, head) LN partial sums
    const float inv0 = 1.f / l0, inv1 = 1.f / l1;
    const int lr0 = w * 16 + g;
    float s0 = 0.f, q0 = 0.f, s1 = 0.f, q1 = 0.f;
    #pragma unroll
    for (int ni = 0; ni < 8; ni++) {
        const int cc = ni * 8 + 2 * t;
        const float f00 = oacc[ni][0] * inv0, f01 = oacc[ni][1] * inv0;
        const float f10 = oacc[ni][2] * inv1, f11 = oacc[ni][3] * inv1;
        s0 += f00 + f01; q0 += f00 * f00 + f01 * f01;
        s1 += f10 + f11; q1 += f10 * f10 + f11 * f11;
        *(uint32_t*)(O + qbase + (size_t)lr0 * DD + cc) = packh2(f00, f01);
        *(uint32_t*)(O + qbase + (size_t)(lr0 + 8) * DD + cc) = packh2(f10, f11);
    }
    s0 += __shfl_xor_sync(0xffffffffu, s0, 1);
    s0 += __shfl_xor_sync(0xffffffffu, s0, 2);
    q0 += __shfl_xor_sync(0xffffffffu, q0, 1);
    q0 += __shfl_xor_sync(0xffffffffu, q0, 2);
    s1 += __shfl_xor_sync(0xffffffffu, s1, 1);
    s1 += __shfl_xor_sync(0xffffffffu, s1, 2);
    q1 += __shfl_xor_sync(0xffffffffu, q1, 1);
    q1 += __shfl_xor_sync(0xffffffffu, q1, 2);
    if (t == 0) {
        const int gr0 = b * NQ + tile * 128 + lr0;
        psum[gr0 * HH + h] = make_float2(s0, q0);
        psum[(gr0 + 8) * HH + h] = make_float2(s1, q1);
    }
}

// ---------------------------------------------------------------------------
// Launch
// ---------------------------------------------------------------------------
extern "C" void kernel_launch(void* const* d_in, const int* in_sizes, int n_in,
                              void* d_out, int out_size)
{
    (void)in_sizes; (void)n_in; (void)out_size;

    const float* q     = (const float*)d_in[0];
    const float* kv    = (const float*)d_in[1];
    const float* Wq    = (const float*)d_in[2];
    const float* Wk    = (const float*)d_in[3];
    const float* Wv    = (const float*)d_in[4];
    const float* Wo    = (const float*)d_in[5];
    const float* bo    = (const float*)d_in[6];
    const float* gamma = (const float*)d_in[7];
    const float* beta  = (const float*)d_in[8];
    float* out = (float*)d_out;

    __half *qh, *kh, *vh, *attn, *wt;
    float2 *psum;
    cudaGetSymbolAddress((void**)&qh,   g_qh);
    cudaGetSymbolAddress((void**)&kh,   g_kh);
    cudaGetSymbolAddress((void**)&vh,   g_vh);
    cudaGetSymbolAddress((void**)&attn, g_attn);
    cudaGetSymbolAddress((void**)&psum, g_psum);
    cudaGetSymbolAddress((void**)&wt,   g_wt);

    cudaFuncSetAttribute(attn_f16,
                         cudaFuncAttributeMaxDynamicSharedMemorySize,
                         ATTN_SMEM_BYTES);

    const __half* wtq = wt;
    const __half* wtk = wt + 1 * DD * DD;
    const __half* wtv = wt + 2 * DD * DD;
    const __half* wto = wt + 3 * DD * DD;

    // Transpose + fp16-convert all weights (Wq pre-scaled by 1/8)
    {
        dim3 grid(DD / 32, DD / 32, 4);
        transpose_w<<<grid, dim3(32, 8)>>>(Wq, Wk, Wv, Wo, wt);
    }
    // All three projections in one launch
    {
        dim3 grid(DD / 128, 96, 1);
        proj_gemm<<<grid, 256>>>(q, kv, wtq, wtk, wtv, qh, kh, vh);
    }
    // Attention (writes fp16 O + LN partial sums)
    {
        dim3 grid(NQ / 128, HH, BB);
        attn_f16<<<grid, 256, ATTN_SMEM_BYTES>>>(qh, kh, vh, attn, psum);
    }
    // Output projection with fused LN + bias
    {
        dim3 grid(DD / 128, (BB * NQ) / 128, 1);
        out_gemm<<<grid, 256>>>(attn, wto, bo, psum, gamma, beta, out);
    }
}